// round 4
// baseline (speedup 1.0000x reference)
#include <cuda_runtime.h>

#define NN 50000
#define EE 600000
#define HH 128
#define GG 2048
#define FIN 11
#define LL 5
#define EPSV 1e-5f

// ---------------- scratch (static device globals) ----------------
__device__ float  g_dinv[NN];
__device__ int    g_cnt[NN];
__device__ int    g_off[NN + 1];
__device__ int    g_cur[NN];
__device__ int    g_csr_src[EE];
__device__ float  g_csr_nrm[EE];
__device__ float4 g_h[NN * (HH / 4)];   // node features (post-GEMM), [N][32] float4
__device__ float4 g_x[NN * (HH / 4)];   // node features (post-agg),  [N][32] float4
__device__ float  g_pool[GG * HH];
__device__ float  g_pcnt[GG];

// ---------------- degree / CSR build ----------------
__global__ void k_zero_cnt() {
    int i = blockIdx.x * blockDim.x + threadIdx.x;
    if (i < NN) g_cnt[i] = 0;
}

__global__ void k_count(const int* __restrict__ ei) {
    int e = blockIdx.x * blockDim.x + threadIdx.x;
    if (e < EE) atomicAdd(&g_cnt[ei[EE + e]], 1);
}

__global__ void k_dinv() {
    int i = blockIdx.x * blockDim.x + threadIdx.x;
    if (i < NN) g_dinv[i] = rsqrtf((float)g_cnt[i] + 1.0f);  // +1 self-loop
}

// single-block scan -> exclusive offsets (N=50000, 49 tiles of 1024)
__global__ void k_scan() {
    __shared__ int sh[1024];
    __shared__ int carry;
    int t = threadIdx.x;
    if (t == 0) carry = 0;
    __syncthreads();
    for (int base = 0; base < NN; base += 1024) {
        int i = base + t;
        int v = (i < NN) ? g_cnt[i] : 0;
        sh[t] = v;
        __syncthreads();
        for (int d = 1; d < 1024; d <<= 1) {
            int x = (t >= d) ? sh[t - d] : 0;
            __syncthreads();
            sh[t] += x;
            __syncthreads();
        }
        int excl = sh[t] - v + carry;
        if (i < NN) { g_off[i] = excl; g_cur[i] = excl; }
        __syncthreads();
        if (t == 1023) carry += sh[1023];
        __syncthreads();
    }
    if (t == 0) g_off[NN] = carry;
}

__global__ void k_fill(const int* __restrict__ ei) {
    int e = blockIdx.x * blockDim.x + threadIdx.x;
    if (e < EE) {
        int s = ei[e];
        int d = ei[EE + e];
        int p = atomicAdd(&g_cur[d], 1);
        g_csr_src[p] = s;
        g_csr_nrm[p] = g_dinv[s] * g_dinv[d];
    }
}

// ---------------- GEMM: layer 0 (K = 11), writes g_h ----------------
__global__ void k_gemm0(const float* __restrict__ X, const float* __restrict__ W0) {
    __shared__ float sW[FIN * HH];
    __shared__ float sx[16 * FIN];
    int t = threadIdx.x;
    int rowBase = blockIdx.x * 16;
    for (int idx = t; idx < FIN * HH; idx += 256) sW[idx] = W0[idx];
    if (t < 16 * FIN) {
        int r = rowBase + t / FIN;
        sx[t] = (r < NN) ? X[r * FIN + (t % FIN)] : 0.0f;
    }
    __syncthreads();
    int c = t & 127;
    int rh = t >> 7;  // 0 or 1
    float w[FIN];
    #pragma unroll
    for (int k = 0; k < FIN; k++) w[k] = sW[k * HH + c];
    float* hout = (float*)g_h;
    #pragma unroll
    for (int i = 0; i < 8; i++) {
        int rloc = rh + 2 * i;
        int r = rowBase + rloc;
        if (r < NN) {
            float acc = 0.0f;
            #pragma unroll
            for (int k = 0; k < FIN; k++) acc += sx[rloc * FIN + k] * w[k];
            hout[r * HH + c] = acc;
        }
    }
}

// ---------------- GEMM: 128x128 (layers 1..4): g_x @ W -> g_h, M-tile = 64 ----------------
__global__ void k_gemm128(const float* __restrict__ W) {
    __shared__ float4 sW4[32 * 32];   // K-chunk(32) x 128 cols   (float4 cols)
    __shared__ float4 sX4[64 * 8];    // 64 rows x K-chunk(32)    (float4)
    int t = threadIdx.x;              // 256
    int rowBase = blockIdx.x * 64;
    int ty = t >> 5, tx = t & 31;

    float acc[8][4];
    #pragma unroll
    for (int r = 0; r < 8; r++)
        #pragma unroll
        for (int c = 0; c < 4; c++) acc[r][c] = 0.0f;

    const float4* W4 = (const float4*)W;
    const float*  sX = (const float*)sX4;

    for (int kc = 0; kc < 4; kc++) {
        #pragma unroll
        for (int i = 0; i < 4; i++) {
            int idx = t + 256 * i;                 // [0,1024)
            int kr = idx >> 5;                     // 0..31
            int c4 = idx & 31;
            sW4[idx] = W4[(kc * 32 + kr) * 32 + c4];
        }
        #pragma unroll
        for (int i = 0; i < 2; i++) {
            int idx = t + 256 * i;                 // [0,512)
            int r = idx >> 3;                      // 0..63
            int c4 = idx & 7;                      // 0..7
            int gr = rowBase + r;
            sX4[idx] = (gr < NN) ? g_x[gr * 32 + kc * 8 + c4]
                                 : make_float4(0.f, 0.f, 0.f, 0.f);
        }
        __syncthreads();
        #pragma unroll 8
        for (int k = 0; k < 32; k++) {
            float4 w = sW4[k * 32 + tx];
            #pragma unroll
            for (int rr = 0; rr < 8; rr++) {
                float xv = sX[(ty * 8 + rr) * 32 + k];
                acc[rr][0] += xv * w.x;
                acc[rr][1] += xv * w.y;
                acc[rr][2] += xv * w.z;
                acc[rr][3] += xv * w.w;
            }
        }
        __syncthreads();
    }

    #pragma unroll
    for (int rr = 0; rr < 8; rr++) {
        int r = rowBase + ty * 8 + rr;
        if (r < NN)
            g_h[r * 32 + tx] = make_float4(acc[rr][0], acc[rr][1], acc[rr][2], acc[rr][3]);
    }
}

// ---------------- aggregation + bias + BN + ReLU + residual ----------------
// warp per node, float4 per lane
__global__ void k_agg(const float* __restrict__ bvec,
                      const float* __restrict__ gamma, const float* __restrict__ beta,
                      const float* __restrict__ mean,  const float* __restrict__ var,
                      int residual) {
    int gwarp = (blockIdx.x * blockDim.x + threadIdx.x) >> 5;
    if (gwarp >= NN) return;
    int lane = threadIdx.x & 31;
    int i = gwarp;

    float di = g_dinv[i];
    float self = di * di;
    float4 hv = g_h[i * 32 + lane];
    float4 acc = make_float4(hv.x * self, hv.y * self, hv.z * self, hv.w * self);

    int s0 = g_off[i], s1 = g_off[i + 1];
    for (int e = s0; e < s1; e++) {
        int s = g_csr_src[e];
        float w = g_csr_nrm[e];
        float4 v = g_h[s * 32 + lane];
        acc.x += w * v.x;
        acc.y += w * v.y;
        acc.z += w * v.z;
        acc.w += w * v.w;
    }

    int c0 = 4 * lane;
    float b0v = bvec[c0],  b1v = bvec[c0 + 1], b2v = bvec[c0 + 2], b3v = bvec[c0 + 3];
    float g0 = gamma[c0],  g1 = gamma[c0 + 1], g2 = gamma[c0 + 2], g3 = gamma[c0 + 3];
    float t0 = beta[c0],   t1 = beta[c0 + 1],  t2 = beta[c0 + 2],  t3 = beta[c0 + 3];
    float m0 = mean[c0],   m1 = mean[c0 + 1],  m2 = mean[c0 + 2],  m3 = mean[c0 + 3];
    float v0 = var[c0],    v1 = var[c0 + 1],   v2 = var[c0 + 2],   v3 = var[c0 + 3];

    float s0c = g0 * rsqrtf(v0 + EPSV), s1c = g1 * rsqrtf(v1 + EPSV);
    float s2c = g2 * rsqrtf(v2 + EPSV), s3c = g3 * rsqrtf(v3 + EPSV);

    float4 r;
    r.x = fmaxf((acc.x + b0v - m0) * s0c + t0, 0.0f);
    r.y = fmaxf((acc.y + b1v - m1) * s1c + t1, 0.0f);
    r.z = fmaxf((acc.z + b2v - m2) * s2c + t2, 0.0f);
    r.w = fmaxf((acc.w + b3v - m3) * s3c + t3, 0.0f);

    if (residual) {
        float4 xp = g_x[i * 32 + lane];
        r.x += xp.x; r.y += xp.y; r.z += xp.z; r.w += xp.w;
    }
    g_x[i * 32 + lane] = r;
}

// ---------------- pooling ----------------
__global__ void k_pool_zero() {
    int i = blockIdx.x * blockDim.x + threadIdx.x;
    if (i < GG * HH) g_pool[i] = 0.0f;
    if (i < GG) g_pcnt[i] = 0.0f;
}

__global__ void k_pool(const int* __restrict__ batch) {
    int gwarp = (blockIdx.x * blockDim.x + threadIdx.x) >> 5;
    if (gwarp >= NN) return;
    int lane = threadIdx.x & 31;
    int b = batch[gwarp];
    float4 v = g_x[gwarp * 32 + lane];
    float* dst = &g_pool[b * HH + 4 * lane];
    atomicAdd(dst + 0, v.x);
    atomicAdd(dst + 1, v.y);
    atomicAdd(dst + 2, v.z);
    atomicAdd(dst + 3, v.w);
    if (lane == 0) atomicAdd(&g_pcnt[b], 1.0f);
}

// ---------------- MLP head ----------------
__global__ void k_mlp(const float* __restrict__ l1w, const float* __restrict__ l1b,
                      const float* __restrict__ l2w, const float* __restrict__ l2b,
                      float* __restrict__ out) {
    int g = blockIdx.x;
    int t = threadIdx.x;  // 64
    __shared__ float sp[HH];
    __shared__ float red[64];
    float inv = 1.0f / fmaxf(g_pcnt[g], 1.0f);
    sp[t]      = g_pool[g * HH + t] * inv;
    sp[t + 64] = g_pool[g * HH + 64 + t] * inv;
    __syncthreads();
    float acc = l1b[t];
    #pragma unroll 8
    for (int k = 0; k < HH; k++) acc += sp[k] * l1w[k * 64 + t];
    float h1 = fmaxf(acc, 0.0f);
    red[t] = h1 * l2w[t];
    __syncthreads();
    for (int s = 32; s > 0; s >>= 1) {
        if (t < s) red[t] += red[t + s];
        __syncthreads();
    }
    if (t == 0) out[g] = red[0] + l2b[0];
}

// ---------------- launch ----------------
extern "C" void kernel_launch(void* const* d_in, const int* in_sizes, int n_in,
                              void* d_out, int out_size) {
    const float* x     = (const float*)d_in[0];
    const int*   ei    = (const int*)d_in[1];     // int32 (JAX default, no x64)
    const int*   batch = (const int*)d_in[2];     // int32
    const float* W0    = (const float*)d_in[3];
    const float* b0    = (const float*)d_in[4];
    const float* Ws    = (const float*)d_in[5];
    const float* bs    = (const float*)d_in[6];
    const float* gam   = (const float*)d_in[7];
    const float* bet   = (const float*)d_in[8];
    const float* mean  = (const float*)d_in[9];
    const float* var   = (const float*)d_in[10];
    const float* l1w   = (const float*)d_in[11];
    const float* l1b   = (const float*)d_in[12];
    const float* l2w   = (const float*)d_in[13];
    const float* l2b   = (const float*)d_in[14];
    float* out = (float*)d_out;

    // graph prep
    k_zero_cnt<<<(NN + 255) / 256, 256>>>();
    k_count<<<(EE + 255) / 256, 256>>>(ei);
    k_dinv<<<(NN + 255) / 256, 256>>>();
    k_scan<<<1, 1024>>>();
    k_fill<<<(EE + 255) / 256, 256>>>(ei);

    // layer 0
    k_gemm0<<<(NN + 15) / 16, 256>>>(x, W0);
    k_agg<<<(NN * 32 + 255) / 256, 256>>>(b0, gam, bet, mean, var, 0);

    // layers 1..4
    for (int l = 1; l < LL; l++) {
        const float* W = Ws + (l - 1) * HH * HH;
        const float* b = bs + (l - 1) * HH;
        k_gemm128<<<(NN + 63) / 64, 256>>>(W);
        k_agg<<<(NN * 32 + 255) / 256, 256>>>(b, gam + l * HH, bet + l * HH,
                                              mean + l * HH, var + l * HH, 1);
    }

    // pooling + head
    k_pool_zero<<<(GG * HH + 255) / 256, 256>>>();
    k_pool<<<(NN * 32 + 255) / 256, 256>>>(batch);
    k_mlp<<<GG, 64>>>(l1w, l1b, l2w, l2b, out);
}

// round 5
// speedup vs baseline: 1.0267x; 1.0267x over previous
#include <cuda_runtime.h>

#define NN 50000
#define EE 600000
#define HH 128
#define GG 2048
#define FIN 11
#define LL 5
#define EPSV 1e-5f

// ---------------- scratch (static device globals) ----------------
__device__ float  g_dinv[NN];
__device__ int    g_cnt[NN];
__device__ int    g_off[NN + 1];
__device__ int    g_cur[NN];
__device__ int    g_csr_src[EE];
__device__ float  g_csr_nrm[EE];
__device__ float4 g_h[NN * (HH / 4)];   // node features (post-GEMM), [N][32] float4
__device__ float4 g_x[NN * (HH / 4)];   // node features (post-agg),  [N][32] float4
__device__ int    g_start[GG + 1];      // per-graph node ranges (batch is sorted)

// ---------------- degree / CSR build ----------------
__global__ void k_zero_cnt() {
    int i = blockIdx.x * blockDim.x + threadIdx.x;
    if (i < NN) g_cnt[i] = 0;
}

__global__ void k_count(const int* __restrict__ ei) {
    int e = blockIdx.x * blockDim.x + threadIdx.x;
    if (e < EE) atomicAdd(&g_cnt[ei[EE + e]], 1);
}

__global__ void k_dinv() {
    int i = blockIdx.x * blockDim.x + threadIdx.x;
    if (i < NN) g_dinv[i] = rsqrtf((float)g_cnt[i] + 1.0f);  // +1 self-loop
}

// fast single-block scan: 1024 threads x 49-elem sequential chunks + shuffle scan
__global__ void k_scan_fast() {
    const int CH = 49;  // 1024*49 = 50176 >= NN
    int t = threadIdx.x;
    int lane = t & 31, wid = t >> 5;
    int base = t * CH;

    int s = 0;
    #pragma unroll
    for (int j = 0; j < CH; j++) {
        int i = base + j;
        if (i < NN) s += g_cnt[i];
    }

    // warp inclusive scan
    int v = s;
    #pragma unroll
    for (int d = 1; d < 32; d <<= 1) {
        int n = __shfl_up_sync(0xFFFFFFFF, v, d);
        if (lane >= d) v += n;
    }
    __shared__ int wsum[32];
    if (lane == 31) wsum[wid] = v;
    __syncthreads();
    if (wid == 0) {
        int w = wsum[lane];
        #pragma unroll
        for (int d = 1; d < 32; d <<= 1) {
            int n = __shfl_up_sync(0xFFFFFFFF, w, d);
            if (lane >= d) w += n;
        }
        wsum[lane] = w;
    }
    __syncthreads();

    int excl = v - s + (wid > 0 ? wsum[wid - 1] : 0);
    int run = excl;
    #pragma unroll
    for (int j = 0; j < CH; j++) {
        int i = base + j;
        if (i < NN) {
            g_off[i] = run;
            g_cur[i] = run;
            run += g_cnt[i];
        }
    }
    if (t == 1023) g_off[NN] = wsum[31];
}

__global__ void k_fill(const int* __restrict__ ei) {
    int e = blockIdx.x * blockDim.x + threadIdx.x;
    if (e < EE) {
        int s = ei[e];
        int d = ei[EE + e];
        int p = atomicAdd(&g_cur[d], 1);
        g_csr_src[p] = s;
        g_csr_nrm[p] = g_dinv[s] * g_dinv[d];
    }
}

// per-graph boundaries from sorted batch vector
__global__ void k_bounds(const int* __restrict__ batch) {
    int i = blockIdx.x * blockDim.x + threadIdx.x;
    if (i >= NN) return;
    int b = batch[i];
    if (i == 0) {
        for (int g = 0; g <= b; g++) g_start[g] = 0;
    } else {
        int pb = batch[i - 1];
        for (int g = pb + 1; g <= b; g++) g_start[g] = i;
    }
    if (i == NN - 1) {
        for (int g = b + 1; g <= GG; g++) g_start[g] = NN;
    }
}

// ---------------- GEMM: layer 0 (K = 11), writes g_h ----------------
__global__ void k_gemm0(const float* __restrict__ X, const float* __restrict__ W0) {
    __shared__ float sW[FIN * HH];
    __shared__ float sx[16 * FIN];
    int t = threadIdx.x;
    int rowBase = blockIdx.x * 16;
    for (int idx = t; idx < FIN * HH; idx += 256) sW[idx] = W0[idx];
    if (t < 16 * FIN) {
        int r = rowBase + t / FIN;
        sx[t] = (r < NN) ? X[r * FIN + (t % FIN)] : 0.0f;
    }
    __syncthreads();
    int c = t & 127;
    int rh = t >> 7;
    float w[FIN];
    #pragma unroll
    for (int k = 0; k < FIN; k++) w[k] = sW[k * HH + c];
    float* hout = (float*)g_h;
    #pragma unroll
    for (int i = 0; i < 8; i++) {
        int rloc = rh + 2 * i;
        int r = rowBase + rloc;
        if (r < NN) {
            float acc = 0.0f;
            #pragma unroll
            for (int k = 0; k < FIN; k++) acc += sx[rloc * FIN + k] * w[k];
            hout[r * HH + c] = acc;
        }
    }
}

// ---------------- GEMM: 128x128 (layers 1..4): g_x @ W -> g_h, M-tile = 64 ----------------
__global__ void k_gemm128(const float* __restrict__ W) {
    __shared__ float4 sW4[32 * 32];
    __shared__ float4 sX4[64 * 8];
    int t = threadIdx.x;              // 256
    int rowBase = blockIdx.x * 64;
    int ty = t >> 5, tx = t & 31;

    float acc[8][4];
    #pragma unroll
    for (int r = 0; r < 8; r++)
        #pragma unroll
        for (int c = 0; c < 4; c++) acc[r][c] = 0.0f;

    const float4* W4 = (const float4*)W;
    const float*  sX = (const float*)sX4;

    for (int kc = 0; kc < 4; kc++) {
        #pragma unroll
        for (int i = 0; i < 4; i++) {
            int idx = t + 256 * i;
            int kr = idx >> 5;
            int c4 = idx & 31;
            sW4[idx] = W4[(kc * 32 + kr) * 32 + c4];
        }
        #pragma unroll
        for (int i = 0; i < 2; i++) {
            int idx = t + 256 * i;
            int r = idx >> 3;
            int c4 = idx & 7;
            int gr = rowBase + r;
            sX4[idx] = (gr < NN) ? g_x[gr * 32 + kc * 8 + c4]
                                 : make_float4(0.f, 0.f, 0.f, 0.f);
        }
        __syncthreads();
        #pragma unroll 8
        for (int k = 0; k < 32; k++) {
            float4 w = sW4[k * 32 + tx];
            #pragma unroll
            for (int rr = 0; rr < 8; rr++) {
                float xv = sX[(ty * 8 + rr) * 32 + k];
                acc[rr][0] += xv * w.x;
                acc[rr][1] += xv * w.y;
                acc[rr][2] += xv * w.z;
                acc[rr][3] += xv * w.w;
            }
        }
        __syncthreads();
    }

    #pragma unroll
    for (int rr = 0; rr < 8; rr++) {
        int r = rowBase + ty * 8 + rr;
        if (r < NN)
            g_h[r * 32 + tx] = make_float4(acc[rr][0], acc[rr][1], acc[rr][2], acc[rr][3]);
    }
}

// ---------------- aggregation + bias + BN + ReLU + residual ----------------
__global__ void k_agg(const float* __restrict__ bvec,
                      const float* __restrict__ gamma, const float* __restrict__ beta,
                      const float* __restrict__ mean,  const float* __restrict__ var,
                      int residual) {
    int gwarp = (blockIdx.x * blockDim.x + threadIdx.x) >> 5;
    if (gwarp >= NN) return;
    int lane = threadIdx.x & 31;
    int i = gwarp;

    float di = g_dinv[i];
    float self = di * di;
    float4 hv = g_h[i * 32 + lane];
    float4 acc = make_float4(hv.x * self, hv.y * self, hv.z * self, hv.w * self);

    int s0 = g_off[i], s1 = g_off[i + 1];
    for (int e = s0; e < s1; e++) {
        int s = g_csr_src[e];
        float w = g_csr_nrm[e];
        float4 v = g_h[s * 32 + lane];
        acc.x += w * v.x;
        acc.y += w * v.y;
        acc.z += w * v.z;
        acc.w += w * v.w;
    }

    int c0 = 4 * lane;
    float b0v = bvec[c0],  b1v = bvec[c0 + 1], b2v = bvec[c0 + 2], b3v = bvec[c0 + 3];
    float g0 = gamma[c0],  g1 = gamma[c0 + 1], g2 = gamma[c0 + 2], g3 = gamma[c0 + 3];
    float t0 = beta[c0],   t1 = beta[c0 + 1],  t2 = beta[c0 + 2],  t3 = beta[c0 + 3];
    float m0 = mean[c0],   m1 = mean[c0 + 1],  m2 = mean[c0 + 2],  m3 = mean[c0 + 3];
    float v0 = var[c0],    v1 = var[c0 + 1],   v2 = var[c0 + 2],   v3 = var[c0 + 3];

    float s0c = g0 * rsqrtf(v0 + EPSV), s1c = g1 * rsqrtf(v1 + EPSV);
    float s2c = g2 * rsqrtf(v2 + EPSV), s3c = g3 * rsqrtf(v3 + EPSV);

    float4 r;
    r.x = fmaxf((acc.x + b0v - m0) * s0c + t0, 0.0f);
    r.y = fmaxf((acc.y + b1v - m1) * s1c + t1, 0.0f);
    r.z = fmaxf((acc.z + b2v - m2) * s2c + t2, 0.0f);
    r.w = fmaxf((acc.w + b3v - m3) * s3c + t3, 0.0f);

    if (residual) {
        float4 xp = g_x[i * 32 + lane];
        r.x += xp.x; r.y += xp.y; r.z += xp.z; r.w += xp.w;
    }
    g_x[i * 32 + lane] = r;
}

// ---------------- fused pooling + MLP head (block per graph) ----------------
__global__ void k_pool_mlp(const float* __restrict__ l1w, const float* __restrict__ l1b,
                           const float* __restrict__ l2w, const float* __restrict__ l2b,
                           float* __restrict__ out) {
    int g = blockIdx.x;
    int t = threadIdx.x;  // 128
    __shared__ float sp[HH];
    __shared__ float red[64];

    int s = g_start[g], e = g_start[g + 1];
    const float* xf = (const float*)g_x;
    float sum = 0.0f;
    for (int r = s; r < e; r++) sum += xf[r * HH + t];
    float inv = 1.0f / fmaxf((float)(e - s), 1.0f);
    sp[t] = sum * inv;
    __syncthreads();

    if (t < 64) {
        float acc = l1b[t];
        #pragma unroll 8
        for (int k = 0; k < HH; k++) acc += sp[k] * l1w[k * 64 + t];
        float h1 = fmaxf(acc, 0.0f);
        red[t] = h1 * l2w[t];
    }
    __syncthreads();
    if (t < 32) {
        float v = red[t] + red[t + 32];
        #pragma unroll
        for (int d = 16; d > 0; d >>= 1) v += __shfl_down_sync(0xFFFFFFFF, v, d);
        if (t == 0) out[g] = v + l2b[0];
    }
}

// ---------------- launch ----------------
extern "C" void kernel_launch(void* const* d_in, const int* in_sizes, int n_in,
                              void* d_out, int out_size) {
    const float* x     = (const float*)d_in[0];
    const int*   ei    = (const int*)d_in[1];
    const int*   batch = (const int*)d_in[2];
    const float* W0    = (const float*)d_in[3];
    const float* b0    = (const float*)d_in[4];
    const float* Ws    = (const float*)d_in[5];
    const float* bs    = (const float*)d_in[6];
    const float* gam   = (const float*)d_in[7];
    const float* bet   = (const float*)d_in[8];
    const float* mean  = (const float*)d_in[9];
    const float* var   = (const float*)d_in[10];
    const float* l1w   = (const float*)d_in[11];
    const float* l1b   = (const float*)d_in[12];
    const float* l2w   = (const float*)d_in[13];
    const float* l2b   = (const float*)d_in[14];
    float* out = (float*)d_out;

    // graph prep
    k_zero_cnt<<<(NN + 255) / 256, 256>>>();
    k_count<<<(EE + 255) / 256, 256>>>(ei);
    k_dinv<<<(NN + 255) / 256, 256>>>();
    k_scan_fast<<<1, 1024>>>();
    k_fill<<<(EE + 255) / 256, 256>>>(ei);
    k_bounds<<<(NN + 255) / 256, 256>>>(batch);

    // layer 0
    k_gemm0<<<(NN + 15) / 16, 256>>>(x, W0);
    k_agg<<<(NN * 32 + 255) / 256, 256>>>(b0, gam, bet, mean, var, 0);

    // layers 1..4
    for (int l = 1; l < LL; l++) {
        const float* W = Ws + (l - 1) * HH * HH;
        const float* b = bs + (l - 1) * HH;
        k_gemm128<<<(NN + 63) / 64, 256>>>(W);
        k_agg<<<(NN * 32 + 255) / 256, 256>>>(b, gam + l * HH, bet + l * HH,
                                              mean + l * HH, var + l * HH, 1);
    }

    // fused pooling + head
    k_pool_mlp<<<GG, 128>>>(l1w, l1b, l2w, l2b, out);
}

// round 6
// speedup vs baseline: 1.2647x; 1.2319x over previous
#include <cuda_runtime.h>

#define NN 50000
#define EE 600000
#define HH 128
#define GG 2048
#define FIN 11
#define LL 5
#define EPSV 1e-5f
#define SCAN_B 49   // ceil(NN/1024)

// ---------------- scratch (static device globals) ----------------
__device__ float  g_dinv[NN];
__device__ int    g_cnt[NN];
__device__ int    g_off[NN + 1];
__device__ int    g_cur[NN];
__device__ int    g_csr_src[EE];
__device__ float  g_csr_nrm[EE];
__device__ float4 g_h[NN * (HH / 4)];   // node features (post-GEMM), [N][32] float4
__device__ float4 g_x[NN * (HH / 4)];   // node features (post-agg),  [N][32] float4
__device__ int    g_start[GG + 1];      // per-graph node ranges (batch is sorted)
__device__ int    g_part[64];
__device__ int    g_pscan[64];

// ---------------- packed f32x2 helpers (Blackwell FFMA2) ----------------
__device__ __forceinline__ unsigned long long pk2(float a, float b) {
    unsigned long long r;
    asm("mov.b64 %0, {%1, %2};" : "=l"(r) : "f"(a), "f"(b));
    return r;
}
__device__ __forceinline__ void fma2(unsigned long long& d, unsigned long long a,
                                     unsigned long long b) {
    asm("fma.rn.f32x2 %0, %1, %2, %0;" : "+l"(d) : "l"(a), "l"(b));
}
__device__ __forceinline__ float2 upk2(unsigned long long p) {
    float2 r;
    asm("mov.b64 {%0, %1}, %2;" : "=f"(r.x), "=f"(r.y) : "l"(p));
    return r;
}

// ---------------- degree / CSR build ----------------
__global__ void k_zero_cnt() {
    int i = blockIdx.x * blockDim.x + threadIdx.x;
    if (i < NN) g_cnt[i] = 0;
}

__global__ void k_count(const int* __restrict__ ei) {
    int e = blockIdx.x * blockDim.x + threadIdx.x;
    if (e < EE) atomicAdd(&g_cnt[ei[EE + e]], 1);
}

__global__ void k_dinv() {
    int i = blockIdx.x * blockDim.x + threadIdx.x;
    if (i < NN) g_dinv[i] = rsqrtf((float)g_cnt[i] + 1.0f);  // +1 self-loop
}

// ---- coalesced 3-phase scan ----
__global__ void k_scan1() {   // 49 blocks x 1024: local exclusive scan + block total
    int t = threadIdx.x, b = blockIdx.x;
    int i = b * 1024 + t;
    int v = (i < NN) ? g_cnt[i] : 0;
    int lane = t & 31, wid = t >> 5;
    int x = v;
    #pragma unroll
    for (int d = 1; d < 32; d <<= 1) {
        int n = __shfl_up_sync(0xFFFFFFFF, x, d);
        if (lane >= d) x += n;
    }
    __shared__ int ws[32];
    if (lane == 31) ws[wid] = x;
    __syncthreads();
    if (wid == 0) {
        int w = ws[lane];
        #pragma unroll
        for (int d = 1; d < 32; d <<= 1) {
            int n = __shfl_up_sync(0xFFFFFFFF, w, d);
            if (lane >= d) w += n;
        }
        ws[lane] = w;
    }
    __syncthreads();
    int incl = x + (wid ? ws[wid - 1] : 0);
    if (i < NN) g_off[i] = incl - v;          // local exclusive
    if (t == 1023) g_part[b] = incl;          // block total
}

__global__ void k_scan2() {   // 1 warp: scan 49 partials
    int lane = threadIdx.x;   // 32
    int a0 = (2 * lane     < SCAN_B) ? g_part[2 * lane]     : 0;
    int a1 = (2 * lane + 1 < SCAN_B) ? g_part[2 * lane + 1] : 0;
    int s = a0 + a1;
    int x = s;
    #pragma unroll
    for (int d = 1; d < 32; d <<= 1) {
        int n = __shfl_up_sync(0xFFFFFFFF, x, d);
        if (lane >= d) x += n;
    }
    int excl = x - s;
    if (2 * lane     < SCAN_B) g_pscan[2 * lane]     = excl;
    if (2 * lane + 1 < SCAN_B) g_pscan[2 * lane + 1] = excl + a0;
    if (lane == 31) g_off[NN] = x;            // grand total
}

__global__ void k_scan3() {   // add block offsets
    int i = blockIdx.x * blockDim.x + threadIdx.x;
    if (i < NN) {
        int o = g_off[i] + g_pscan[i >> 10];
        g_off[i] = o;
        g_cur[i] = o;
    }
}

__global__ void k_fill(const int* __restrict__ ei) {
    int e = blockIdx.x * blockDim.x + threadIdx.x;
    if (e < EE) {
        int s = ei[e];
        int d = ei[EE + e];
        int p = atomicAdd(&g_cur[d], 1);
        g_csr_src[p] = s;
        g_csr_nrm[p] = g_dinv[s] * g_dinv[d];
    }
}

// per-graph boundaries from sorted batch vector
__global__ void k_bounds(const int* __restrict__ batch) {
    int i = blockIdx.x * blockDim.x + threadIdx.x;
    if (i >= NN) return;
    int b = batch[i];
    if (i == 0) {
        for (int g = 0; g <= b; g++) g_start[g] = 0;
    } else {
        int pb = batch[i - 1];
        for (int g = pb + 1; g <= b; g++) g_start[g] = i;
    }
    if (i == NN - 1) {
        for (int g = b + 1; g <= GG; g++) g_start[g] = NN;
    }
}

// ---------------- GEMM: layer 0 (K = 11), writes g_h ----------------
__global__ void k_gemm0(const float* __restrict__ X, const float* __restrict__ W0) {
    __shared__ float sW[FIN * HH];
    __shared__ float sx[16 * FIN];
    int t = threadIdx.x;
    int rowBase = blockIdx.x * 16;
    for (int idx = t; idx < FIN * HH; idx += 256) sW[idx] = W0[idx];
    if (t < 16 * FIN) {
        int r = rowBase + t / FIN;
        sx[t] = (r < NN) ? X[r * FIN + (t % FIN)] : 0.0f;
    }
    __syncthreads();
    int c = t & 127;
    int rh = t >> 7;
    float w[FIN];
    #pragma unroll
    for (int k = 0; k < FIN; k++) w[k] = sW[k * HH + c];
    float* hout = (float*)g_h;
    #pragma unroll
    for (int i = 0; i < 8; i++) {
        int rloc = rh + 2 * i;
        int r = rowBase + rloc;
        if (r < NN) {
            float acc = 0.0f;
            #pragma unroll
            for (int k = 0; k < FIN; k++) acc += sx[rloc * FIN + k] * w[k];
            hout[r * HH + c] = acc;
        }
    }
}

// ---------------- GEMM 128x128 via packed f32x2 FMA: g_x @ W -> g_h, M-tile 64 ----------------
__global__ void k_gemm128(const float* __restrict__ W) {
    __shared__ float4 sW4[32 * 32];                 // [k][col4]  16 KB
    __shared__ __align__(16) float sXT[32 * 64];    // [k][row]    8 KB (transposed)
    int t = threadIdx.x;              // 256
    int rowBase = blockIdx.x * 64;
    int ty = t >> 5, tx = t & 31;

    unsigned long long acc[4][4];     // [row-pair][col]; each packs 2 rows
    #pragma unroll
    for (int p = 0; p < 4; p++)
        #pragma unroll
        for (int c = 0; c < 4; c++) acc[p][c] = 0ULL;

    const float4* W4 = (const float4*)W;

    for (int kc = 0; kc < 4; kc++) {
        #pragma unroll
        for (int i = 0; i < 4; i++) {
            int idx = t + 256 * i;                 // [0,1024)
            int kr = idx >> 5;
            int c4 = idx & 31;
            sW4[idx] = W4[(kc * 32 + kr) * 32 + c4];
        }
        #pragma unroll
        for (int i = 0; i < 2; i++) {
            int idx = t + 256 * i;                 // [0,512)
            int r = idx >> 3;                      // 0..63
            int c4 = idx & 7;                      // 0..7 (k-group of 4)
            int gr = rowBase + r;
            float4 v = (gr < NN) ? g_x[gr * 32 + kc * 8 + c4]
                                 : make_float4(0.f, 0.f, 0.f, 0.f);
            int kb = c4 * 4;
            sXT[(kb + 0) * 64 + r] = v.x;
            sXT[(kb + 1) * 64 + r] = v.y;
            sXT[(kb + 2) * 64 + r] = v.z;
            sXT[(kb + 3) * 64 + r] = v.w;
        }
        __syncthreads();
        #pragma unroll
        for (int k = 0; k < 32; k++) {
            float4 w = sW4[k * 32 + tx];
            unsigned long long w0 = pk2(w.x, w.x);
            unsigned long long w1 = pk2(w.y, w.y);
            unsigned long long w2 = pk2(w.z, w.z);
            unsigned long long w3 = pk2(w.w, w.w);
            const ulonglong2* xr = (const ulonglong2*)&sXT[k * 64 + ty * 8];
            ulonglong2 xa = xr[0];    // rows (0,1),(2,3) of this thread's 8
            ulonglong2 xb = xr[1];    // rows (4,5),(6,7)
            fma2(acc[0][0], xa.x, w0); fma2(acc[0][1], xa.x, w1);
            fma2(acc[0][2], xa.x, w2); fma2(acc[0][3], xa.x, w3);
            fma2(acc[1][0], xa.y, w0); fma2(acc[1][1], xa.y, w1);
            fma2(acc[1][2], xa.y, w2); fma2(acc[1][3], xa.y, w3);
            fma2(acc[2][0], xb.x, w0); fma2(acc[2][1], xb.x, w1);
            fma2(acc[2][2], xb.x, w2); fma2(acc[2][3], xb.x, w3);
            fma2(acc[3][0], xb.y, w0); fma2(acc[3][1], xb.y, w1);
            fma2(acc[3][2], xb.y, w2); fma2(acc[3][3], xb.y, w3);
        }
        __syncthreads();
    }

    #pragma unroll
    for (int p = 0; p < 4; p++) {
        float2 c0 = upk2(acc[p][0]);
        float2 c1 = upk2(acc[p][1]);
        float2 c2 = upk2(acc[p][2]);
        float2 c3 = upk2(acc[p][3]);
        int r0 = rowBase + ty * 8 + 2 * p;
        int r1 = r0 + 1;
        if (r0 < NN) g_h[r0 * 32 + tx] = make_float4(c0.x, c1.x, c2.x, c3.x);
        if (r1 < NN) g_h[r1 * 32 + tx] = make_float4(c0.y, c1.y, c2.y, c3.y);
    }
}

// ---------------- aggregation + bias + BN + ReLU + residual ----------------
__global__ void k_agg(const float* __restrict__ bvec,
                      const float* __restrict__ gamma, const float* __restrict__ beta,
                      const float* __restrict__ mean,  const float* __restrict__ var,
                      int residual) {
    int gwarp = (blockIdx.x * blockDim.x + threadIdx.x) >> 5;
    if (gwarp >= NN) return;
    int lane = threadIdx.x & 31;
    int i = gwarp;

    float di = g_dinv[i];
    float self = di * di;
    float4 hv = g_h[i * 32 + lane];
    float4 acc = make_float4(hv.x * self, hv.y * self, hv.z * self, hv.w * self);

    int s0 = g_off[i], s1 = g_off[i + 1];
    for (int e = s0; e < s1; e++) {
        int s = g_csr_src[e];
        float w = g_csr_nrm[e];
        float4 v = g_h[s * 32 + lane];
        acc.x += w * v.x;
        acc.y += w * v.y;
        acc.z += w * v.z;
        acc.w += w * v.w;
    }

    int c0 = 4 * lane;
    float b0v = bvec[c0],  b1v = bvec[c0 + 1], b2v = bvec[c0 + 2], b3v = bvec[c0 + 3];
    float g0 = gamma[c0],  g1 = gamma[c0 + 1], g2 = gamma[c0 + 2], g3 = gamma[c0 + 3];
    float t0 = beta[c0],   t1 = beta[c0 + 1],  t2 = beta[c0 + 2],  t3 = beta[c0 + 3];
    float m0 = mean[c0],   m1 = mean[c0 + 1],  m2 = mean[c0 + 2],  m3 = mean[c0 + 3];
    float v0 = var[c0],    v1 = var[c0 + 1],   v2 = var[c0 + 2],   v3 = var[c0 + 3];

    float s0c = g0 * rsqrtf(v0 + EPSV), s1c = g1 * rsqrtf(v1 + EPSV);
    float s2c = g2 * rsqrtf(v2 + EPSV), s3c = g3 * rsqrtf(v3 + EPSV);

    float4 r;
    r.x = fmaxf((acc.x + b0v - m0) * s0c + t0, 0.0f);
    r.y = fmaxf((acc.y + b1v - m1) * s1c + t1, 0.0f);
    r.z = fmaxf((acc.z + b2v - m2) * s2c + t2, 0.0f);
    r.w = fmaxf((acc.w + b3v - m3) * s3c + t3, 0.0f);

    if (residual) {
        float4 xp = g_x[i * 32 + lane];
        r.x += xp.x; r.y += xp.y; r.z += xp.z; r.w += xp.w;
    }
    g_x[i * 32 + lane] = r;
}

// ---------------- fused pooling + MLP head (block per graph) ----------------
__global__ void k_pool_mlp(const float* __restrict__ l1w, const float* __restrict__ l1b,
                           const float* __restrict__ l2w, const float* __restrict__ l2b,
                           float* __restrict__ out) {
    int g = blockIdx.x;
    int t = threadIdx.x;  // 128
    __shared__ float sp[HH];
    __shared__ float red[64];

    int s = g_start[g], e = g_start[g + 1];
    const float* xf = (const float*)g_x;
    float sum = 0.0f;
    for (int r = s; r < e; r++) sum += xf[r * HH + t];
    float inv = 1.0f / fmaxf((float)(e - s), 1.0f);
    sp[t] = sum * inv;
    __syncthreads();

    if (t < 64) {
        float acc = l1b[t];
        #pragma unroll 8
        for (int k = 0; k < HH; k++) acc += sp[k] * l1w[k * 64 + t];
        float h1 = fmaxf(acc, 0.0f);
        red[t] = h1 * l2w[t];
    }
    __syncthreads();
    if (t < 32) {
        float v = red[t] + red[t + 32];
        #pragma unroll
        for (int d = 16; d > 0; d >>= 1) v += __shfl_down_sync(0xFFFFFFFF, v, d);
        if (t == 0) out[g] = v + l2b[0];
    }
}

// ---------------- launch ----------------
extern "C" void kernel_launch(void* const* d_in, const int* in_sizes, int n_in,
                              void* d_out, int out_size) {
    const float* x     = (const float*)d_in[0];
    const int*   ei    = (const int*)d_in[1];
    const int*   batch = (const int*)d_in[2];
    const float* W0    = (const float*)d_in[3];
    const float* b0    = (const float*)d_in[4];
    const float* Ws    = (const float*)d_in[5];
    const float* bs    = (const float*)d_in[6];
    const float* gam   = (const float*)d_in[7];
    const float* bet   = (const float*)d_in[8];
    const float* mean  = (const float*)d_in[9];
    const float* var   = (const float*)d_in[10];
    const float* l1w   = (const float*)d_in[11];
    const float* l1b   = (const float*)d_in[12];
    const float* l2w   = (const float*)d_in[13];
    const float* l2b   = (const float*)d_in[14];
    float* out = (float*)d_out;

    // graph prep
    k_zero_cnt<<<(NN + 255) / 256, 256>>>();
    k_count<<<(EE + 255) / 256, 256>>>(ei);
    k_dinv<<<(NN + 255) / 256, 256>>>();
    k_scan1<<<SCAN_B, 1024>>>();
    k_scan2<<<1, 32>>>();
    k_scan3<<<(NN + 255) / 256, 256>>>();
    k_fill<<<(EE + 255) / 256, 256>>>(ei);
    k_bounds<<<(NN + 255) / 256, 256>>>(batch);

    // layer 0
    k_gemm0<<<(NN + 15) / 16, 256>>>(x, W0);
    k_agg<<<(NN * 32 + 255) / 256, 256>>>(b0, gam, bet, mean, var, 0);

    // layers 1..4
    for (int l = 1; l < LL; l++) {
        const float* W = Ws + (l - 1) * HH * HH;
        const float* b = bs + (l - 1) * HH;
        k_gemm128<<<(NN + 63) / 64, 256>>>(W);
        k_agg<<<(NN * 32 + 255) / 256, 256>>>(b, gam + l * HH, bet + l * HH,
                                              mean + l * HH, var + l * HH, 1);
    }

    // fused pooling + head
    k_pool_mlp<<<GG, 128>>>(l1w, l1b, l2w, l2b, out);
}

// round 7
// speedup vs baseline: 1.3387x; 1.0585x over previous
#include <cuda_runtime.h>

#define NN 50000
#define EE 600000
#define HH 128
#define GG 2048
#define FIN 11
#define LL 5
#define EPSV 1e-5f
#define SCAN_B 49   // ceil(NN/1024)

// ---------------- scratch (static device globals) ----------------
__device__ float  g_dinv[NN];
__device__ int    g_cnt[NN];
__device__ int    g_off[NN + 1];
__device__ int    g_cur[NN];
__device__ int2   g_csr[EE];            // {src, nrm-bits}
__device__ float4 g_h[NN * (HH / 4)];   // node features (post-GEMM), [N][32] float4
__device__ float4 g_x[NN * (HH / 4)];   // node features (post-agg),  [N][32] float4
__device__ int    g_start[GG + 1];      // per-graph node ranges (batch is sorted)
__device__ int    g_part[64];
__device__ int    g_pscan[64];

// ---------------- tf32 helpers ----------------
__device__ __forceinline__ void tf32split(float x, unsigned& hi, unsigned& lo) {
    asm("cvt.rna.tf32.f32 %0, %1;" : "=r"(hi) : "f"(x));
    float r = x - __uint_as_float(hi);
    asm("cvt.rna.tf32.f32 %0, %1;" : "=r"(lo) : "f"(r));
}
__device__ __forceinline__ void mma_tf32(float* d, const unsigned* a, const unsigned* b) {
    asm volatile(
        "mma.sync.aligned.m16n8k8.row.col.f32.tf32.tf32.f32 "
        "{%0,%1,%2,%3}, {%4,%5,%6,%7}, {%8,%9}, {%0,%1,%2,%3};"
        : "+f"(d[0]), "+f"(d[1]), "+f"(d[2]), "+f"(d[3])
        : "r"(a[0]), "r"(a[1]), "r"(a[2]), "r"(a[3]), "r"(b[0]), "r"(b[1]));
}

// ---------------- degree / CSR build ----------------
__global__ void k_zero_cnt() {
    int i = blockIdx.x * blockDim.x + threadIdx.x;
    if (i < NN) g_cnt[i] = 0;
}

__global__ void k_count(const int* __restrict__ ei) {
    int e = blockIdx.x * blockDim.x + threadIdx.x;
    if (e < EE) atomicAdd(&g_cnt[ei[EE + e]], 1);
}

__global__ void k_dinv() {
    int i = blockIdx.x * blockDim.x + threadIdx.x;
    if (i < NN) g_dinv[i] = rsqrtf((float)g_cnt[i] + 1.0f);  // +1 self-loop
}

// ---- coalesced 3-phase scan ----
__global__ void k_scan1() {
    int t = threadIdx.x, b = blockIdx.x;
    int i = b * 1024 + t;
    int v = (i < NN) ? g_cnt[i] : 0;
    int lane = t & 31, wid = t >> 5;
    int x = v;
    #pragma unroll
    for (int d = 1; d < 32; d <<= 1) {
        int n = __shfl_up_sync(0xFFFFFFFF, x, d);
        if (lane >= d) x += n;
    }
    __shared__ int ws[32];
    if (lane == 31) ws[wid] = x;
    __syncthreads();
    if (wid == 0) {
        int w = ws[lane];
        #pragma unroll
        for (int d = 1; d < 32; d <<= 1) {
            int n = __shfl_up_sync(0xFFFFFFFF, w, d);
            if (lane >= d) w += n;
        }
        ws[lane] = w;
    }
    __syncthreads();
    int incl = x + (wid ? ws[wid - 1] : 0);
    if (i < NN) g_off[i] = incl - v;
    if (t == 1023) g_part[b] = incl;
}

__global__ void k_scan2() {
    int lane = threadIdx.x;   // 32
    int a0 = (2 * lane     < SCAN_B) ? g_part[2 * lane]     : 0;
    int a1 = (2 * lane + 1 < SCAN_B) ? g_part[2 * lane + 1] : 0;
    int s = a0 + a1;
    int x = s;
    #pragma unroll
    for (int d = 1; d < 32; d <<= 1) {
        int n = __shfl_up_sync(0xFFFFFFFF, x, d);
        if (lane >= d) x += n;
    }
    int excl = x - s;
    if (2 * lane     < SCAN_B) g_pscan[2 * lane]     = excl;
    if (2 * lane + 1 < SCAN_B) g_pscan[2 * lane + 1] = excl + a0;
    if (lane == 31) g_off[NN] = x;
}

__global__ void k_scan3() {
    int i = blockIdx.x * blockDim.x + threadIdx.x;
    if (i < NN) {
        int o = g_off[i] + g_pscan[i >> 10];
        g_off[i] = o;
        g_cur[i] = o;
    }
}

__global__ void k_fill(const int* __restrict__ ei) {
    int e = blockIdx.x * blockDim.x + threadIdx.x;
    if (e < EE) {
        int s = ei[e];
        int d = ei[EE + e];
        int p = atomicAdd(&g_cur[d], 1);
        g_csr[p] = make_int2(s, __float_as_int(g_dinv[s] * g_dinv[d]));
    }
}

// per-graph boundaries from sorted batch vector
__global__ void k_bounds(const int* __restrict__ batch) {
    int i = blockIdx.x * blockDim.x + threadIdx.x;
    if (i >= NN) return;
    int b = batch[i];
    if (i == 0) {
        for (int g = 0; g <= b; g++) g_start[g] = 0;
    } else {
        int pb = batch[i - 1];
        for (int g = pb + 1; g <= b; g++) g_start[g] = i;
    }
    if (i == NN - 1) {
        for (int g = b + 1; g <= GG; g++) g_start[g] = NN;
    }
}

// ---------------- GEMM: layer 0 (K = 11), writes g_h ----------------
__global__ void k_gemm0(const float* __restrict__ X, const float* __restrict__ W0) {
    __shared__ float sW[FIN * HH];
    __shared__ float sx[16 * FIN];
    int t = threadIdx.x;
    int rowBase = blockIdx.x * 16;
    for (int idx = t; idx < FIN * HH; idx += 256) sW[idx] = W0[idx];
    if (t < 16 * FIN) {
        int r = rowBase + t / FIN;
        sx[t] = (r < NN) ? X[r * FIN + (t % FIN)] : 0.0f;
    }
    __syncthreads();
    int c = t & 127;
    int rh = t >> 7;
    float w[FIN];
    #pragma unroll
    for (int k = 0; k < FIN; k++) w[k] = sW[k * HH + c];
    float* hout = (float*)g_h;
    #pragma unroll
    for (int i = 0; i < 8; i++) {
        int rloc = rh + 2 * i;
        int r = rowBase + rloc;
        if (r < NN) {
            float acc = 0.0f;
            #pragma unroll
            for (int k = 0; k < FIN; k++) acc += sx[rloc * FIN + k] * w[k];
            hout[r * HH + c] = acc;
        }
    }
}

// ---------------- GEMM 128x128 via 3xTF32 tensor cores: g_x @ W -> g_h ----------------
// CTA: 256 thr (8 warps), tile M=128 x N=128, K chunked by 32.
// Warp grid 4(M) x 2(N); warp tile 32 rows x 64 cols = 2 x 8 m16n8 frags.
__global__ void __launch_bounds__(256) k_gemm_tc(const float* __restrict__ W) {
    __shared__ float sA[128][36];    // [row][k], pitch 36 -> conflict-free A frags
    __shared__ float sB[32][136];    // [k][n],   pitch 136 -> conflict-free B frags
    int t = threadIdx.x;
    int rowBase = blockIdx.x * 128;
    int lane = t & 31, w = t >> 5;
    int wm = w >> 1, wn = w & 1;
    int gq = lane >> 2, cq = lane & 3;

    float acc[2][8][4];
    #pragma unroll
    for (int mt = 0; mt < 2; mt++)
        #pragma unroll
        for (int nt = 0; nt < 8; nt++)
            #pragma unroll
            for (int k = 0; k < 4; k++) acc[mt][nt][k] = 0.0f;

    const float4* W4 = (const float4*)W;

    for (int kc = 0; kc < 4; kc++) {
        // load A tile: 128 rows x 32 k (1024 float4)
        #pragma unroll
        for (int i = 0; i < 4; i++) {
            int idx = t + 256 * i;
            int r = idx >> 3, c4 = idx & 7;
            int gr = rowBase + r;
            float4 v = (gr < NN) ? g_x[gr * 32 + kc * 8 + c4]
                                 : make_float4(0.f, 0.f, 0.f, 0.f);
            *(float4*)&sA[r][c4 * 4] = v;
        }
        // load B tile (W rows kc*32..+32): 32 x 128 (1024 float4)
        #pragma unroll
        for (int i = 0; i < 4; i++) {
            int idx = t + 256 * i;
            int kr = idx >> 5, n4 = idx & 31;
            float4 v = W4[(kc * 32 + kr) * 32 + n4];
            *(float4*)&sB[kr][n4 * 4] = v;
        }
        __syncthreads();

        #pragma unroll
        for (int ks = 0; ks < 4; ks++) {
            int kb = ks * 8;
            // B fragments: 8 n-tiles
            unsigned bh[8][2], bl[8][2];
            #pragma unroll
            for (int nt = 0; nt < 8; nt++) {
                int n0 = wn * 64 + nt * 8 + gq;
                tf32split(sB[kb + cq][n0],     bh[nt][0], bl[nt][0]);
                tf32split(sB[kb + 4 + cq][n0], bh[nt][1], bl[nt][1]);
            }
            // A fragments: 2 m-tiles
            unsigned ah[2][4], al[2][4];
            #pragma unroll
            for (int mt = 0; mt < 2; mt++) {
                int r0 = wm * 32 + mt * 16 + gq;
                tf32split(sA[r0][kb + cq],         ah[mt][0], al[mt][0]);
                tf32split(sA[r0 + 8][kb + cq],     ah[mt][1], al[mt][1]);
                tf32split(sA[r0][kb + 4 + cq],     ah[mt][2], al[mt][2]);
                tf32split(sA[r0 + 8][kb + 4 + cq], ah[mt][3], al[mt][3]);
            }
            #pragma unroll
            for (int mt = 0; mt < 2; mt++)
                #pragma unroll
                for (int nt = 0; nt < 8; nt++) {
                    mma_tf32(acc[mt][nt], ah[mt], bh[nt]);
                    mma_tf32(acc[mt][nt], ah[mt], bl[nt]);
                    mma_tf32(acc[mt][nt], al[mt], bh[nt]);
                }
        }
        __syncthreads();
    }

    // epilogue: write g_h
    float* hf = (float*)g_h;
    #pragma unroll
    for (int mt = 0; mt < 2; mt++) {
        int r0 = rowBase + wm * 32 + mt * 16 + gq;
        #pragma unroll
        for (int nt = 0; nt < 8; nt++) {
            int col = wn * 64 + nt * 8 + cq * 2;
            if (r0 < NN)
                *(float2*)&hf[r0 * HH + col] = make_float2(acc[mt][nt][0], acc[mt][nt][1]);
            if (r0 + 8 < NN)
                *(float2*)&hf[(r0 + 8) * HH + col] = make_float2(acc[mt][nt][2], acc[mt][nt][3]);
        }
    }
}

// ---------------- aggregation + bias + BN + ReLU + residual ----------------
__global__ void k_agg(const float* __restrict__ bvec,
                      const float* __restrict__ gamma, const float* __restrict__ beta,
                      const float* __restrict__ mean,  const float* __restrict__ var,
                      int residual) {
    int gwarp = (blockIdx.x * blockDim.x + threadIdx.x) >> 5;
    if (gwarp >= NN) return;
    int lane = threadIdx.x & 31;
    int i = gwarp;

    float di = g_dinv[i];
    float self = di * di;
    float4 hv = g_h[i * 32 + lane];
    float4 acc = make_float4(hv.x * self, hv.y * self, hv.z * self, hv.w * self);

    int s0 = g_off[i], s1 = g_off[i + 1];
    for (int e = s0; e < s1; e++) {
        int2 se = g_csr[e];
        float w = __int_as_float(se.y);
        float4 v = g_h[se.x * 32 + lane];
        acc.x += w * v.x;
        acc.y += w * v.y;
        acc.z += w * v.z;
        acc.w += w * v.w;
    }

    int c0 = 4 * lane;
    float b0v = bvec[c0],  b1v = bvec[c0 + 1], b2v = bvec[c0 + 2], b3v = bvec[c0 + 3];
    float g0 = gamma[c0],  g1 = gamma[c0 + 1], g2 = gamma[c0 + 2], g3 = gamma[c0 + 3];
    float t0 = beta[c0],   t1 = beta[c0 + 1],  t2 = beta[c0 + 2],  t3 = beta[c0 + 3];
    float m0 = mean[c0],   m1 = mean[c0 + 1],  m2 = mean[c0 + 2],  m3 = mean[c0 + 3];
    float v0 = var[c0],    v1 = var[c0 + 1],   v2 = var[c0 + 2],   v3 = var[c0 + 3];

    float s0c = g0 * rsqrtf(v0 + EPSV), s1c = g1 * rsqrtf(v1 + EPSV);
    float s2c = g2 * rsqrtf(v2 + EPSV), s3c = g3 * rsqrtf(v3 + EPSV);

    float4 r;
    r.x = fmaxf((acc.x + b0v - m0) * s0c + t0, 0.0f);
    r.y = fmaxf((acc.y + b1v - m1) * s1c + t1, 0.0f);
    r.z = fmaxf((acc.z + b2v - m2) * s2c + t2, 0.0f);
    r.w = fmaxf((acc.w + b3v - m3) * s3c + t3, 0.0f);

    if (residual) {
        float4 xp = g_x[i * 32 + lane];
        r.x += xp.x; r.y += xp.y; r.z += xp.z; r.w += xp.w;
    }
    g_x[i * 32 + lane] = r;
}

// ---------------- fused pooling + MLP head (block per graph) ----------------
__global__ void k_pool_mlp(const float* __restrict__ l1w, const float* __restrict__ l1b,
                           const float* __restrict__ l2w, const float* __restrict__ l2b,
                           float* __restrict__ out) {
    int g = blockIdx.x;
    int t = threadIdx.x;  // 128
    __shared__ float sp[HH];
    __shared__ float red[64];

    int s = g_start[g], e = g_start[g + 1];
    const float* xf = (const float*)g_x;
    float sum = 0.0f;
    for (int r = s; r < e; r++) sum += xf[r * HH + t];
    float inv = 1.0f / fmaxf((float)(e - s), 1.0f);
    sp[t] = sum * inv;
    __syncthreads();

    if (t < 64) {
        float acc = l1b[t];
        #pragma unroll 8
        for (int k = 0; k < HH; k++) acc += sp[k] * l1w[k * 64 + t];
        float h1 = fmaxf(acc, 0.0f);
        red[t] = h1 * l2w[t];
    }
    __syncthreads();
    if (t < 32) {
        float v = red[t] + red[t + 32];
        #pragma unroll
        for (int d = 16; d > 0; d >>= 1) v += __shfl_down_sync(0xFFFFFFFF, v, d);
        if (t == 0) out[g] = v + l2b[0];
    }
}

// ---------------- launch ----------------
extern "C" void kernel_launch(void* const* d_in, const int* in_sizes, int n_in,
                              void* d_out, int out_size) {
    const float* x     = (const float*)d_in[0];
    const int*   ei    = (const int*)d_in[1];
    const int*   batch = (const int*)d_in[2];
    const float* W0    = (const float*)d_in[3];
    const float* b0    = (const float*)d_in[4];
    const float* Ws    = (const float*)d_in[5];
    const float* bs    = (const float*)d_in[6];
    const float* gam   = (const float*)d_in[7];
    const float* bet   = (const float*)d_in[8];
    const float* mean  = (const float*)d_in[9];
    const float* var   = (const float*)d_in[10];
    const float* l1w   = (const float*)d_in[11];
    const float* l1b   = (const float*)d_in[12];
    const float* l2w   = (const float*)d_in[13];
    const float* l2b   = (const float*)d_in[14];
    float* out = (float*)d_out;

    // graph prep
    k_zero_cnt<<<(NN + 255) / 256, 256>>>();
    k_count<<<(EE + 255) / 256, 256>>>(ei);
    k_dinv<<<(NN + 255) / 256, 256>>>();
    k_scan1<<<SCAN_B, 1024>>>();
    k_scan2<<<1, 32>>>();
    k_scan3<<<(NN + 255) / 256, 256>>>();
    k_fill<<<(EE + 255) / 256, 256>>>(ei);
    k_bounds<<<(NN + 255) / 256, 256>>>(batch);

    // layer 0
    k_gemm0<<<(NN + 15) / 16, 256>>>(x, W0);
    k_agg<<<(NN * 32 + 255) / 256, 256>>>(b0, gam, bet, mean, var, 0);

    // layers 1..4 (tensor-core GEMM)
    for (int l = 1; l < LL; l++) {
        const float* W = Ws + (l - 1) * HH * HH;
        const float* b = bs + (l - 1) * HH;
        k_gemm_tc<<<(NN + 127) / 128, 256>>>(W);
        k_agg<<<(NN * 32 + 255) / 256, 256>>>(b, gam + l * HH, bet + l * HH,
                                              mean + l * HH, var + l * HH, 1);
    }

    // fused pooling + head
    k_pool_mlp<<<GG, 128>>>(l1w, l1b, l2w, l2b, out);
}

// round 8
// speedup vs baseline: 1.3777x; 1.0291x over previous
#include <cuda_runtime.h>
#include <cuda_bf16.h>

#define NN 50000
#define EE 600000
#define HH 128
#define GG 2048
#define FIN 11
#define LL 5
#define EPSV 1e-5f
#define SCAN_B 49   // ceil(NN/1024)

// ---------------- scratch (static device globals) ----------------
__device__ float        g_dinv[NN];
__device__ int          g_cnt[NN];
__device__ int          g_off[NN + 1];
__device__ int          g_cur[NN];
__device__ int2         g_csr[EE];            // {src, nrm-bits}
__device__ float4       g_h[NN * (HH / 4)];   // h fp32 (self term)
__device__ unsigned int g_hb[NN * (HH / 2)];  // h bf16x2 (neighbor gathers), [N][64]
__device__ float4       g_x[NN * (HH / 4)];   // post-agg features
__device__ int          g_start[GG + 1];
__device__ int          g_part[64];
__device__ int          g_pscan[64];

// ---------------- tf32 helpers ----------------
__device__ __forceinline__ void tf32split(float x, unsigned& hi, unsigned& lo) {
    asm("cvt.rna.tf32.f32 %0, %1;" : "=r"(hi) : "f"(x));
    float r = x - __uint_as_float(hi);
    asm("cvt.rna.tf32.f32 %0, %1;" : "=r"(lo) : "f"(r));
}
__device__ __forceinline__ void mma_tf32(float* d, const unsigned* a, const unsigned* b) {
    asm volatile(
        "mma.sync.aligned.m16n8k8.row.col.f32.tf32.tf32.f32 "
        "{%0,%1,%2,%3}, {%4,%5,%6,%7}, {%8,%9}, {%0,%1,%2,%3};"
        : "+f"(d[0]), "+f"(d[1]), "+f"(d[2]), "+f"(d[3])
        : "r"(a[0]), "r"(a[1]), "r"(a[2]), "r"(a[3]), "r"(b[0]), "r"(b[1]));
}
__device__ __forceinline__ unsigned packbf2(float a, float b) {
    unsigned r;
    asm("cvt.rn.bf16x2.f32 %0, %1, %2;" : "=r"(r) : "f"(b), "f"(a));
    return r;  // low half = a, high half = b
}

// ---------------- degree / CSR build ----------------
__global__ void k_zero_cnt() {
    int i = blockIdx.x * blockDim.x + threadIdx.x;
    if (i < NN) g_cnt[i] = 0;
}

__global__ void k_count(const int* __restrict__ ei) {
    int e = blockIdx.x * blockDim.x + threadIdx.x;
    if (e < EE) atomicAdd(&g_cnt[ei[EE + e]], 1);
}

__global__ void k_dinv() {
    int i = blockIdx.x * blockDim.x + threadIdx.x;
    if (i < NN) g_dinv[i] = rsqrtf((float)g_cnt[i] + 1.0f);  // +1 self-loop
}

// ---- coalesced 3-phase scan ----
__global__ void k_scan1() {
    int t = threadIdx.x, b = blockIdx.x;
    int i = b * 1024 + t;
    int v = (i < NN) ? g_cnt[i] : 0;
    int lane = t & 31, wid = t >> 5;
    int x = v;
    #pragma unroll
    for (int d = 1; d < 32; d <<= 1) {
        int n = __shfl_up_sync(0xFFFFFFFF, x, d);
        if (lane >= d) x += n;
    }
    __shared__ int ws[32];
    if (lane == 31) ws[wid] = x;
    __syncthreads();
    if (wid == 0) {
        int w = ws[lane];
        #pragma unroll
        for (int d = 1; d < 32; d <<= 1) {
            int n = __shfl_up_sync(0xFFFFFFFF, w, d);
            if (lane >= d) w += n;
        }
        ws[lane] = w;
    }
    __syncthreads();
    int incl = x + (wid ? ws[wid - 1] : 0);
    if (i < NN) g_off[i] = incl - v;
    if (t == 1023) g_part[b] = incl;
}

__global__ void k_scan2() {
    int lane = threadIdx.x;   // 32
    int a0 = (2 * lane     < SCAN_B) ? g_part[2 * lane]     : 0;
    int a1 = (2 * lane + 1 < SCAN_B) ? g_part[2 * lane + 1] : 0;
    int s = a0 + a1;
    int x = s;
    #pragma unroll
    for (int d = 1; d < 32; d <<= 1) {
        int n = __shfl_up_sync(0xFFFFFFFF, x, d);
        if (lane >= d) x += n;
    }
    int excl = x - s;
    if (2 * lane     < SCAN_B) g_pscan[2 * lane]     = excl;
    if (2 * lane + 1 < SCAN_B) g_pscan[2 * lane + 1] = excl + a0;
    if (lane == 31) g_off[NN] = x;
}

__global__ void k_scan3() {
    int i = blockIdx.x * blockDim.x + threadIdx.x;
    if (i < NN) {
        int o = g_off[i] + g_pscan[i >> 10];
        g_off[i] = o;
        g_cur[i] = o;
    }
}

__global__ void k_fill(const int* __restrict__ ei) {
    int e = blockIdx.x * blockDim.x + threadIdx.x;
    if (e < EE) {
        int s = ei[e];
        int d = ei[EE + e];
        int p = atomicAdd(&g_cur[d], 1);
        g_csr[p] = make_int2(s, __float_as_int(g_dinv[s] * g_dinv[d]));
    }
}

// per-graph boundaries from sorted batch vector
__global__ void k_bounds(const int* __restrict__ batch) {
    int i = blockIdx.x * blockDim.x + threadIdx.x;
    if (i >= NN) return;
    int b = batch[i];
    if (i == 0) {
        for (int g = 0; g <= b; g++) g_start[g] = 0;
    } else {
        int pb = batch[i - 1];
        for (int g = pb + 1; g <= b; g++) g_start[g] = i;
    }
    if (i == NN - 1) {
        for (int g = b + 1; g <= GG; g++) g_start[g] = NN;
    }
}

// ---------------- GEMM: layer 0 (K = 11), writes g_h + g_hb ----------------
__global__ void k_gemm0(const float* __restrict__ X, const float* __restrict__ W0) {
    __shared__ float sW[FIN * HH];
    __shared__ float sx[16 * FIN];
    int t = threadIdx.x;
    int rowBase = blockIdx.x * 16;
    for (int idx = t; idx < FIN * HH; idx += 256) sW[idx] = W0[idx];
    if (t < 16 * FIN) {
        int r = rowBase + t / FIN;
        sx[t] = (r < NN) ? X[r * FIN + (t % FIN)] : 0.0f;
    }
    __syncthreads();
    int c = t & 127;
    int rh = t >> 7;
    float w[FIN];
    #pragma unroll
    for (int k = 0; k < FIN; k++) w[k] = sW[k * HH + c];
    float* hout = (float*)g_h;
    #pragma unroll
    for (int i = 0; i < 8; i++) {
        int rloc = rh + 2 * i;
        int r = rowBase + rloc;
        if (r < NN) {
            float acc = 0.0f;
            #pragma unroll
            for (int k = 0; k < FIN; k++) acc += sx[rloc * FIN + k] * w[k];
            hout[r * HH + c] = acc;
            float other = __shfl_xor_sync(0xFFFFFFFF, acc, 1);
            if ((c & 1) == 0)
                g_hb[r * 64 + (c >> 1)] = packbf2(acc, other);
        }
    }
}

// ---------------- GEMM 128x128 via 3xTF32 tensor cores: g_x @ W -> g_h + g_hb ----------------
__global__ void __launch_bounds__(256) k_gemm_tc(const float* __restrict__ W) {
    __shared__ float sA[128][36];
    __shared__ float sB[32][136];
    int t = threadIdx.x;
    int rowBase = blockIdx.x * 128;
    int lane = t & 31, w = t >> 5;
    int wm = w >> 1, wn = w & 1;
    int gq = lane >> 2, cq = lane & 3;

    float acc[2][8][4];
    #pragma unroll
    for (int mt = 0; mt < 2; mt++)
        #pragma unroll
        for (int nt = 0; nt < 8; nt++)
            #pragma unroll
            for (int k = 0; k < 4; k++) acc[mt][nt][k] = 0.0f;

    const float4* W4 = (const float4*)W;

    for (int kc = 0; kc < 4; kc++) {
        #pragma unroll
        for (int i = 0; i < 4; i++) {
            int idx = t + 256 * i;
            int r = idx >> 3, c4 = idx & 7;
            int gr = rowBase + r;
            float4 v = (gr < NN) ? g_x[gr * 32 + kc * 8 + c4]
                                 : make_float4(0.f, 0.f, 0.f, 0.f);
            *(float4*)&sA[r][c4 * 4] = v;
        }
        #pragma unroll
        for (int i = 0; i < 4; i++) {
            int idx = t + 256 * i;
            int kr = idx >> 5, n4 = idx & 31;
            float4 v = W4[(kc * 32 + kr) * 32 + n4];
            *(float4*)&sB[kr][n4 * 4] = v;
        }
        __syncthreads();

        #pragma unroll
        for (int ks = 0; ks < 4; ks++) {
            int kb = ks * 8;
            unsigned bh[8][2], bl[8][2];
            #pragma unroll
            for (int nt = 0; nt < 8; nt++) {
                int n0 = wn * 64 + nt * 8 + gq;
                tf32split(sB[kb + cq][n0],     bh[nt][0], bl[nt][0]);
                tf32split(sB[kb + 4 + cq][n0], bh[nt][1], bl[nt][1]);
            }
            unsigned ah[2][4], al[2][4];
            #pragma unroll
            for (int mt = 0; mt < 2; mt++) {
                int r0 = wm * 32 + mt * 16 + gq;
                tf32split(sA[r0][kb + cq],         ah[mt][0], al[mt][0]);
                tf32split(sA[r0 + 8][kb + cq],     ah[mt][1], al[mt][1]);
                tf32split(sA[r0][kb + 4 + cq],     ah[mt][2], al[mt][2]);
                tf32split(sA[r0 + 8][kb + 4 + cq], ah[mt][3], al[mt][3]);
            }
            #pragma unroll
            for (int mt = 0; mt < 2; mt++)
                #pragma unroll
                for (int nt = 0; nt < 8; nt++) {
                    mma_tf32(acc[mt][nt], ah[mt], bh[nt]);
                    mma_tf32(acc[mt][nt], ah[mt], bl[nt]);
                    mma_tf32(acc[mt][nt], al[mt], bh[nt]);
                }
        }
        __syncthreads();
    }

    // epilogue: write g_h (fp32) + g_hb (bf16x2)
    float* hf = (float*)g_h;
    #pragma unroll
    for (int mt = 0; mt < 2; mt++) {
        int r0 = rowBase + wm * 32 + mt * 16 + gq;
        #pragma unroll
        for (int nt = 0; nt < 8; nt++) {
            int col = wn * 64 + nt * 8 + cq * 2;
            if (r0 < NN) {
                *(float2*)&hf[r0 * HH + col] = make_float2(acc[mt][nt][0], acc[mt][nt][1]);
                g_hb[r0 * 64 + (col >> 1)] = packbf2(acc[mt][nt][0], acc[mt][nt][1]);
            }
            if (r0 + 8 < NN) {
                *(float2*)&hf[(r0 + 8) * HH + col] = make_float2(acc[mt][nt][2], acc[mt][nt][3]);
                g_hb[(r0 + 8) * 64 + (col >> 1)] = packbf2(acc[mt][nt][2], acc[mt][nt][3]);
            }
        }
    }
}

// ---------------- aggregation (bf16 gathers) + bias + BN + ReLU + residual ----------------
__global__ void k_agg(const float* __restrict__ bvec,
                      const float* __restrict__ gamma, const float* __restrict__ beta,
                      const float* __restrict__ mean,  const float* __restrict__ var,
                      int residual) {
    int gwarp = (blockIdx.x * blockDim.x + threadIdx.x) >> 5;
    if (gwarp >= NN) return;
    int lane = threadIdx.x & 31;
    int i = gwarp;

    float di = g_dinv[i];
    float self = di * di;
    float4 hv = g_h[i * 32 + lane];     // exact fp32 self term
    float4 acc = make_float4(hv.x * self, hv.y * self, hv.z * self, hv.w * self);

    int s0 = g_off[i], s1 = g_off[i + 1];
    for (int e = s0; e < s1; e++) {
        int2 se = g_csr[e];
        float w = __int_as_float(se.y);
        uint2 pb = *(const uint2*)&g_hb[se.x * 64 + 2 * lane];
        float v0 = __uint_as_float(pb.x << 16);
        float v1 = __uint_as_float(pb.x & 0xFFFF0000u);
        float v2 = __uint_as_float(pb.y << 16);
        float v3 = __uint_as_float(pb.y & 0xFFFF0000u);
        acc.x += w * v0;
        acc.y += w * v1;
        acc.z += w * v2;
        acc.w += w * v3;
    }

    int c0 = 4 * lane;
    float b0v = bvec[c0],  b1v = bvec[c0 + 1], b2v = bvec[c0 + 2], b3v = bvec[c0 + 3];
    float g0 = gamma[c0],  g1 = gamma[c0 + 1], g2 = gamma[c0 + 2], g3 = gamma[c0 + 3];
    float t0 = beta[c0],   t1 = beta[c0 + 1],  t2 = beta[c0 + 2],  t3 = beta[c0 + 3];
    float m0 = mean[c0],   m1 = mean[c0 + 1],  m2 = mean[c0 + 2],  m3 = mean[c0 + 3];
    float v0 = var[c0],    v1 = var[c0 + 1],   v2 = var[c0 + 2],   v3 = var[c0 + 3];

    float s0c = g0 * rsqrtf(v0 + EPSV), s1c = g1 * rsqrtf(v1 + EPSV);
    float s2c = g2 * rsqrtf(v2 + EPSV), s3c = g3 * rsqrtf(v3 + EPSV);

    float4 r;
    r.x = fmaxf((acc.x + b0v - m0) * s0c + t0, 0.0f);
    r.y = fmaxf((acc.y + b1v - m1) * s1c + t1, 0.0f);
    r.z = fmaxf((acc.z + b2v - m2) * s2c + t2, 0.0f);
    r.w = fmaxf((acc.w + b3v - m3) * s3c + t3, 0.0f);

    if (residual) {
        float4 xp = g_x[i * 32 + lane];
        r.x += xp.x; r.y += xp.y; r.z += xp.z; r.w += xp.w;
    }
    g_x[i * 32 + lane] = r;
}

// ---------------- fused pooling + MLP head (block per graph) ----------------
__global__ void k_pool_mlp(const float* __restrict__ l1w, const float* __restrict__ l1b,
                           const float* __restrict__ l2w, const float* __restrict__ l2b,
                           float* __restrict__ out) {
    int g = blockIdx.x;
    int t = threadIdx.x;  // 128
    __shared__ float sp[HH];
    __shared__ float red[64];

    int s = g_start[g], e = g_start[g + 1];
    const float* xf = (const float*)g_x;
    float sum = 0.0f;
    for (int r = s; r < e; r++) sum += xf[r * HH + t];
    float inv = 1.0f / fmaxf((float)(e - s), 1.0f);
    sp[t] = sum * inv;
    __syncthreads();

    if (t < 64) {
        float acc = l1b[t];
        #pragma unroll 8
        for (int k = 0; k < HH; k++) acc += sp[k] * l1w[k * 64 + t];
        float h1 = fmaxf(acc, 0.0f);
        red[t] = h1 * l2w[t];
    }
    __syncthreads();
    if (t < 32) {
        float v = red[t] + red[t + 32];
        #pragma unroll
        for (int d = 16; d > 0; d >>= 1) v += __shfl_down_sync(0xFFFFFFFF, v, d);
        if (t == 0) out[g] = v + l2b[0];
    }
}

// ---------------- launch ----------------
extern "C" void kernel_launch(void* const* d_in, const int* in_sizes, int n_in,
                              void* d_out, int out_size) {
    const float* x     = (const float*)d_in[0];
    const int*   ei    = (const int*)d_in[1];
    const int*   batch = (const int*)d_in[2];
    const float* W0    = (const float*)d_in[3];
    const float* b0    = (const float*)d_in[4];
    const float* Ws    = (const float*)d_in[5];
    const float* bs    = (const float*)d_in[6];
    const float* gam   = (const float*)d_in[7];
    const float* bet   = (const float*)d_in[8];
    const float* mean  = (const float*)d_in[9];
    const float* var   = (const float*)d_in[10];
    const float* l1w   = (const float*)d_in[11];
    const float* l1b   = (const float*)d_in[12];
    const float* l2w   = (const float*)d_in[13];
    const float* l2b   = (const float*)d_in[14];
    float* out = (float*)d_out;

    // graph prep
    k_zero_cnt<<<(NN + 255) / 256, 256>>>();
    k_count<<<(EE + 255) / 256, 256>>>(ei);
    k_dinv<<<(NN + 255) / 256, 256>>>();
    k_scan1<<<SCAN_B, 1024>>>();
    k_scan2<<<1, 32>>>();
    k_scan3<<<(NN + 255) / 256, 256>>>();
    k_fill<<<(EE + 255) / 256, 256>>>(ei);
    k_bounds<<<(NN + 255) / 256, 256>>>(batch);

    // layer 0
    k_gemm0<<<(NN + 15) / 16, 256>>>(x, W0);
    k_agg<<<(NN * 32 + 255) / 256, 256>>>(b0, gam, bet, mean, var, 0);

    // layers 1..4 (tensor-core GEMM)
    for (int l = 1; l < LL; l++) {
        const float* W = Ws + (l - 1) * HH * HH;
        const float* b = bs + (l - 1) * HH;
        k_gemm_tc<<<(NN + 127) / 128, 256>>>(W);
        k_agg<<<(NN * 32 + 255) / 256, 256>>>(b, gam + l * HH, bet + l * HH,
                                              mean + l * HH, var + l * HH, 1);
    }

    // fused pooling + head
    k_pool_mlp<<<GG, 128>>>(l1w, l1b, l2w, l2b, out);
}

// round 9
// speedup vs baseline: 1.3857x; 1.0058x over previous
#include <cuda_runtime.h>
#include <cuda_bf16.h>

#define NN 50000
#define EE 600000
#define HH 128
#define GG 2048
#define FIN 11
#define LL 5
#define EPSV 1e-5f
#define SCAN_B 49   // ceil(NN/1024)

// ---------------- scratch (static device globals) ----------------
__device__ float        g_dinv[NN];
__device__ int          g_cnt[NN];
__device__ int          g_off[NN + 1];
__device__ int          g_cur[NN];
__device__ int2         g_csr[EE];            // {src, nrm-bits}
__device__ float4       g_h[NN * (HH / 4)];   // h fp32 (self term)
__device__ unsigned int g_hb[NN * (HH / 2)];  // h bf16x2 (neighbor gathers), [N][64]
__device__ float4       g_x[NN * (HH / 4)];   // post-agg features
__device__ int          g_start[GG + 1];
__device__ int          g_part[64];
__device__ int          g_pscan[64];

// ---------------- tf32 helpers ----------------
__device__ __forceinline__ void tf32split(float x, unsigned& hi, unsigned& lo) {
    asm("cvt.rna.tf32.f32 %0, %1;" : "=r"(hi) : "f"(x));
    float r = x - __uint_as_float(hi);
    asm("cvt.rna.tf32.f32 %0, %1;" : "=r"(lo) : "f"(r));
}
__device__ __forceinline__ void mma_tf32(float* d, const unsigned* a, const unsigned* b) {
    asm volatile(
        "mma.sync.aligned.m16n8k8.row.col.f32.tf32.tf32.f32 "
        "{%0,%1,%2,%3}, {%4,%5,%6,%7}, {%8,%9}, {%0,%1,%2,%3};"
        : "+f"(d[0]), "+f"(d[1]), "+f"(d[2]), "+f"(d[3])
        : "r"(a[0]), "r"(a[1]), "r"(a[2]), "r"(a[3]), "r"(b[0]), "r"(b[1]));
}
__device__ __forceinline__ unsigned packbf2(float a, float b) {
    unsigned r;
    asm("cvt.rn.bf16x2.f32 %0, %1, %2;" : "=r"(r) : "f"(b), "f"(a));
    return r;  // low half = a, high half = b
}

// ---------------- degree / CSR build ----------------
__global__ void k_zero_cnt() {
    int i = blockIdx.x * blockDim.x + threadIdx.x;
    if (i < NN) g_cnt[i] = 0;
}

__global__ void k_count(const int* __restrict__ ei) {
    int e = blockIdx.x * blockDim.x + threadIdx.x;
    if (e < EE) atomicAdd(&g_cnt[ei[EE + e]], 1);
}

__global__ void k_dinv() {
    int i = blockIdx.x * blockDim.x + threadIdx.x;
    if (i < NN) g_dinv[i] = rsqrtf((float)g_cnt[i] + 1.0f);  // +1 self-loop
}

// ---- coalesced 3-phase scan ----
__global__ void k_scan1() {
    int t = threadIdx.x, b = blockIdx.x;
    int i = b * 1024 + t;
    int v = (i < NN) ? g_cnt[i] : 0;
    int lane = t & 31, wid = t >> 5;
    int x = v;
    #pragma unroll
    for (int d = 1; d < 32; d <<= 1) {
        int n = __shfl_up_sync(0xFFFFFFFF, x, d);
        if (lane >= d) x += n;
    }
    __shared__ int ws[32];
    if (lane == 31) ws[wid] = x;
    __syncthreads();
    if (wid == 0) {
        int w = ws[lane];
        #pragma unroll
        for (int d = 1; d < 32; d <<= 1) {
            int n = __shfl_up_sync(0xFFFFFFFF, w, d);
            if (lane >= d) w += n;
        }
        ws[lane] = w;
    }
    __syncthreads();
    int incl = x + (wid ? ws[wid - 1] : 0);
    if (i < NN) g_off[i] = incl - v;
    if (t == 1023) g_part[b] = incl;
}

__global__ void k_scan2() {
    int lane = threadIdx.x;   // 32
    int a0 = (2 * lane     < SCAN_B) ? g_part[2 * lane]     : 0;
    int a1 = (2 * lane + 1 < SCAN_B) ? g_part[2 * lane + 1] : 0;
    int s = a0 + a1;
    int x = s;
    #pragma unroll
    for (int d = 1; d < 32; d <<= 1) {
        int n = __shfl_up_sync(0xFFFFFFFF, x, d);
        if (lane >= d) x += n;
    }
    int excl = x - s;
    if (2 * lane     < SCAN_B) g_pscan[2 * lane]     = excl;
    if (2 * lane + 1 < SCAN_B) g_pscan[2 * lane + 1] = excl + a0;
    if (lane == 31) g_off[NN] = x;
}

__global__ void k_scan3() {
    int i = blockIdx.x * blockDim.x + threadIdx.x;
    if (i < NN) {
        int o = g_off[i] + g_pscan[i >> 10];
        g_off[i] = o;
        g_cur[i] = o;
    }
}

__global__ void k_fill(const int* __restrict__ ei) {
    int e = blockIdx.x * blockDim.x + threadIdx.x;
    if (e < EE) {
        int s = ei[e];
        int d = ei[EE + e];
        int p = atomicAdd(&g_cur[d], 1);
        g_csr[p] = make_int2(s, __float_as_int(g_dinv[s] * g_dinv[d]));
    }
}

// per-graph boundaries from sorted batch vector
__global__ void k_bounds(const int* __restrict__ batch) {
    int i = blockIdx.x * blockDim.x + threadIdx.x;
    if (i >= NN) return;
    int b = batch[i];
    if (i == 0) {
        for (int g = 0; g <= b; g++) g_start[g] = 0;
    } else {
        int pb = batch[i - 1];
        for (int g = pb + 1; g <= b; g++) g_start[g] = i;
    }
    if (i == NN - 1) {
        for (int g = b + 1; g <= GG; g++) g_start[g] = NN;
    }
}

// ---------------- GEMM: layer 0 (K = 11), writes g_h + g_hb ----------------
__global__ void k_gemm0(const float* __restrict__ X, const float* __restrict__ W0) {
    __shared__ float sW[FIN * HH];
    __shared__ float sx[16 * FIN];
    int t = threadIdx.x;
    int rowBase = blockIdx.x * 16;
    for (int idx = t; idx < FIN * HH; idx += 256) sW[idx] = W0[idx];
    if (t < 16 * FIN) {
        int r = rowBase + t / FIN;
        sx[t] = (r < NN) ? X[r * FIN + (t % FIN)] : 0.0f;
    }
    __syncthreads();
    int c = t & 127;
    int rh = t >> 7;
    float w[FIN];
    #pragma unroll
    for (int k = 0; k < FIN; k++) w[k] = sW[k * HH + c];
    float* hout = (float*)g_h;
    #pragma unroll
    for (int i = 0; i < 8; i++) {
        int rloc = rh + 2 * i;
        int r = rowBase + rloc;
        if (r < NN) {
            float acc = 0.0f;
            #pragma unroll
            for (int k = 0; k < FIN; k++) acc += sx[rloc * FIN + k] * w[k];
            hout[r * HH + c] = acc;
            float other = __shfl_xor_sync(0xFFFFFFFF, acc, 1);
            if ((c & 1) == 0)
                g_hb[r * 64 + (c >> 1)] = packbf2(acc, other);
        }
    }
}

// ---------------- GEMM 128x128, 3xTF32 TC, split-at-load: g_x @ W -> g_h + g_hb ----------------
// K chunked by 16; A/B pre-split to tf32 hi/lo in smem; inner loop = LDS + MMA only.
__global__ void __launch_bounds__(256) k_gemm_tc(const float* __restrict__ W) {
    __shared__ unsigned sAh[128][20], sAl[128][20];   // [row][k] pitch 20 (4r+k banks)
    __shared__ unsigned sBh[16][136], sBl[16][136];   // [k][n]  pitch 136 (8k+n banks)
    int t = threadIdx.x;
    int rowBase = blockIdx.x * 128;
    int lane = t & 31, w = t >> 5;
    int wm = w >> 1, wn = w & 1;
    int gq = lane >> 2, cq = lane & 3;

    float acc[2][8][4];
    #pragma unroll
    for (int mt = 0; mt < 2; mt++)
        #pragma unroll
        for (int nt = 0; nt < 8; nt++)
            #pragma unroll
            for (int k = 0; k < 4; k++) acc[mt][nt][k] = 0.0f;

    const float4* W4 = (const float4*)W;

    for (int kc = 0; kc < 8; kc++) {
        // A: 128 rows x 16 k = 512 float4, split at load
        #pragma unroll
        for (int i = 0; i < 2; i++) {
            int idx = t + 256 * i;             // 0..511
            int r = idx >> 2, c4 = idx & 3;    // 4 float4 per row
            int gr = rowBase + r;
            float4 v = (gr < NN) ? g_x[gr * 32 + kc * 4 + c4]
                                 : make_float4(0.f, 0.f, 0.f, 0.f);
            unsigned h0, l0, h1, l1, h2, l2, h3, l3;
            tf32split(v.x, h0, l0); tf32split(v.y, h1, l1);
            tf32split(v.z, h2, l2); tf32split(v.w, h3, l3);
            int cb = c4 * 4;
            sAh[r][cb] = h0; sAh[r][cb + 1] = h1; sAh[r][cb + 2] = h2; sAh[r][cb + 3] = h3;
            sAl[r][cb] = l0; sAl[r][cb + 1] = l1; sAl[r][cb + 2] = l2; sAl[r][cb + 3] = l3;
        }
        // B: 16 k x 128 n = 512 float4, split at load
        #pragma unroll
        for (int i = 0; i < 2; i++) {
            int idx = t + 256 * i;
            int kr = idx >> 5, n4 = idx & 31;
            float4 v = W4[(kc * 16 + kr) * 32 + n4];
            unsigned h0, l0, h1, l1, h2, l2, h3, l3;
            tf32split(v.x, h0, l0); tf32split(v.y, h1, l1);
            tf32split(v.z, h2, l2); tf32split(v.w, h3, l3);
            int nb = n4 * 4;
            sBh[kr][nb] = h0; sBh[kr][nb + 1] = h1; sBh[kr][nb + 2] = h2; sBh[kr][nb + 3] = h3;
            sBl[kr][nb] = l0; sBl[kr][nb + 1] = l1; sBl[kr][nb + 2] = l2; sBl[kr][nb + 3] = l3;
        }
        __syncthreads();

        #pragma unroll
        for (int ks = 0; ks < 2; ks++) {
            int kb = ks * 8;
            unsigned bh[8][2], bl[8][2];
            #pragma unroll
            for (int nt = 0; nt < 8; nt++) {
                int n0 = wn * 64 + nt * 8 + gq;
                bh[nt][0] = sBh[kb + cq][n0];
                bh[nt][1] = sBh[kb + 4 + cq][n0];
                bl[nt][0] = sBl[kb + cq][n0];
                bl[nt][1] = sBl[kb + 4 + cq][n0];
            }
            unsigned ah[2][4], al[2][4];
            #pragma unroll
            for (int mt = 0; mt < 2; mt++) {
                int r0 = wm * 32 + mt * 16 + gq;
                ah[mt][0] = sAh[r0][kb + cq];
                ah[mt][1] = sAh[r0 + 8][kb + cq];
                ah[mt][2] = sAh[r0][kb + 4 + cq];
                ah[mt][3] = sAh[r0 + 8][kb + 4 + cq];
                al[mt][0] = sAl[r0][kb + cq];
                al[mt][1] = sAl[r0 + 8][kb + cq];
                al[mt][2] = sAl[r0][kb + 4 + cq];
                al[mt][3] = sAl[r0 + 8][kb + 4 + cq];
            }
            #pragma unroll
            for (int mt = 0; mt < 2; mt++)
                #pragma unroll
                for (int nt = 0; nt < 8; nt++) {
                    mma_tf32(acc[mt][nt], ah[mt], bh[nt]);
                    mma_tf32(acc[mt][nt], ah[mt], bl[nt]);
                    mma_tf32(acc[mt][nt], al[mt], bh[nt]);
                }
        }
        __syncthreads();
    }

    // epilogue: write g_h (fp32) + g_hb (bf16x2)
    float* hf = (float*)g_h;
    #pragma unroll
    for (int mt = 0; mt < 2; mt++) {
        int r0 = rowBase + wm * 32 + mt * 16 + gq;
        #pragma unroll
        for (int nt = 0; nt < 8; nt++) {
            int col = wn * 64 + nt * 8 + cq * 2;
            if (r0 < NN) {
                *(float2*)&hf[r0 * HH + col] = make_float2(acc[mt][nt][0], acc[mt][nt][1]);
                g_hb[r0 * 64 + (col >> 1)] = packbf2(acc[mt][nt][0], acc[mt][nt][1]);
            }
            if (r0 + 8 < NN) {
                *(float2*)&hf[(r0 + 8) * HH + col] = make_float2(acc[mt][nt][2], acc[mt][nt][3]);
                g_hb[(r0 + 8) * 64 + (col >> 1)] = packbf2(acc[mt][nt][2], acc[mt][nt][3]);
            }
        }
    }
}

// ---------------- aggregation (bf16 gathers, 4x unrolled) + bias + BN + ReLU + residual ----
__device__ __forceinline__ void bf2fma(float4& acc, float w, uint2 pb) {
    acc.x += w * __uint_as_float(pb.x << 16);
    acc.y += w * __uint_as_float(pb.x & 0xFFFF0000u);
    acc.z += w * __uint_as_float(pb.y << 16);
    acc.w += w * __uint_as_float(pb.y & 0xFFFF0000u);
}

__global__ void k_agg(const float* __restrict__ bvec,
                      const float* __restrict__ gamma, const float* __restrict__ beta,
                      const float* __restrict__ mean,  const float* __restrict__ var,
                      int residual) {
    int gwarp = (blockIdx.x * blockDim.x + threadIdx.x) >> 5;
    if (gwarp >= NN) return;
    int lane = threadIdx.x & 31;
    int i = gwarp;

    float di = g_dinv[i];
    float self = di * di;
    float4 hv = g_h[i * 32 + lane];     // exact fp32 self term
    float4 acc = make_float4(hv.x * self, hv.y * self, hv.z * self, hv.w * self);

    int s0 = g_off[i], s1 = g_off[i + 1];
    int e = s0;
    const unsigned* hb = g_hb;
    for (; e + 4 <= s1; e += 4) {
        int2 sa = g_csr[e];
        int2 sb = g_csr[e + 1];
        int2 sc = g_csr[e + 2];
        int2 sd = g_csr[e + 3];
        uint2 pa = *(const uint2*)&hb[sa.x * 64 + 2 * lane];
        uint2 pb = *(const uint2*)&hb[sb.x * 64 + 2 * lane];
        uint2 pc = *(const uint2*)&hb[sc.x * 64 + 2 * lane];
        uint2 pd = *(const uint2*)&hb[sd.x * 64 + 2 * lane];
        bf2fma(acc, __int_as_float(sa.y), pa);
        bf2fma(acc, __int_as_float(sb.y), pb);
        bf2fma(acc, __int_as_float(sc.y), pc);
        bf2fma(acc, __int_as_float(sd.y), pd);
    }
    for (; e < s1; e++) {
        int2 se = g_csr[e];
        uint2 pe = *(const uint2*)&hb[se.x * 64 + 2 * lane];
        bf2fma(acc, __int_as_float(se.y), pe);
    }

    int c0 = 4 * lane;
    float b0v = bvec[c0],  b1v = bvec[c0 + 1], b2v = bvec[c0 + 2], b3v = bvec[c0 + 3];
    float g0 = gamma[c0],  g1 = gamma[c0 + 1], g2 = gamma[c0 + 2], g3 = gamma[c0 + 3];
    float t0 = beta[c0],   t1 = beta[c0 + 1],  t2 = beta[c0 + 2],  t3 = beta[c0 + 3];
    float m0 = mean[c0],   m1 = mean[c0 + 1],  m2 = mean[c0 + 2],  m3 = mean[c0 + 3];
    float v0 = var[c0],    v1 = var[c0 + 1],   v2 = var[c0 + 2],   v3 = var[c0 + 3];

    float s0c = g0 * rsqrtf(v0 + EPSV), s1c = g1 * rsqrtf(v1 + EPSV);
    float s2c = g2 * rsqrtf(v2 + EPSV), s3c = g3 * rsqrtf(v3 + EPSV);

    float4 r;
    r.x = fmaxf((acc.x + b0v - m0) * s0c + t0, 0.0f);
    r.y = fmaxf((acc.y + b1v - m1) * s1c + t1, 0.0f);
    r.z = fmaxf((acc.z + b2v - m2) * s2c + t2, 0.0f);
    r.w = fmaxf((acc.w + b3v - m3) * s3c + t3, 0.0f);

    if (residual) {
        float4 xp = g_x[i * 32 + lane];
        r.x += xp.x; r.y += xp.y; r.z += xp.z; r.w += xp.w;
    }
    g_x[i * 32 + lane] = r;
}

// ---------------- fused pooling + MLP head (block per graph) ----------------
__global__ void k_pool_mlp(const float* __restrict__ l1w, const float* __restrict__ l1b,
                           const float* __restrict__ l2w, const float* __restrict__ l2b,
                           float* __restrict__ out) {
    int g = blockIdx.x;
    int t = threadIdx.x;  // 128
    __shared__ float sp[HH];
    __shared__ float red[64];

    int s = g_start[g], e = g_start[g + 1];
    const float* xf = (const float*)g_x;
    float sum = 0.0f;
    for (int r = s; r < e; r++) sum += xf[r * HH + t];
    float inv = 1.0f / fmaxf((float)(e - s), 1.0f);
    sp[t] = sum * inv;
    __syncthreads();

    if (t < 64) {
        float acc = l1b[t];
        #pragma unroll 8
        for (int k = 0; k < HH; k++) acc += sp[k] * l1w[k * 64 + t];
        float h1 = fmaxf(acc, 0.0f);
        red[t] = h1 * l2w[t];
    }
    __syncthreads();
    if (t < 32) {
        float v = red[t] + red[t + 32];
        #pragma unroll
        for (int d = 16; d > 0; d >>= 1) v += __shfl_down_sync(0xFFFFFFFF, v, d);
        if (t == 0) out[g] = v + l2b[0];
    }
}

// ---------------- launch ----------------
extern "C" void kernel_launch(void* const* d_in, const int* in_sizes, int n_in,
                              void* d_out, int out_size) {
    const float* x     = (const float*)d_in[0];
    const int*   ei    = (const int*)d_in[1];
    const int*   batch = (const int*)d_in[2];
    const float* W0    = (const float*)d_in[3];
    const float* b0    = (const float*)d_in[4];
    const float* Ws    = (const float*)d_in[5];
    const float* bs    = (const float*)d_in[6];
    const float* gam   = (const float*)d_in[7];
    const float* bet   = (const float*)d_in[8];
    const float* mean  = (const float*)d_in[9];
    const float* var   = (const float*)d_in[10];
    const float* l1w   = (const float*)d_in[11];
    const float* l1b   = (const float*)d_in[12];
    const float* l2w   = (const float*)d_in[13];
    const float* l2b   = (const float*)d_in[14];
    float* out = (float*)d_out;

    // graph prep
    k_zero_cnt<<<(NN + 255) / 256, 256>>>();
    k_count<<<(EE + 255) / 256, 256>>>(ei);
    k_dinv<<<(NN + 255) / 256, 256>>>();
    k_scan1<<<SCAN_B, 1024>>>();
    k_scan2<<<1, 32>>>();
    k_scan3<<<(NN + 255) / 256, 256>>>();
    k_fill<<<(EE + 255) / 256, 256>>>(ei);
    k_bounds<<<(NN + 255) / 256, 256>>>(batch);

    // layer 0
    k_gemm0<<<(NN + 15) / 16, 256>>>(x, W0);
    k_agg<<<(NN * 32 + 255) / 256, 256>>>(b0, gam, bet, mean, var, 0);

    // layers 1..4 (tensor-core GEMM)
    for (int l = 1; l < LL; l++) {
        const float* W = Ws + (l - 1) * HH * HH;
        const float* b = bs + (l - 1) * HH;
        k_gemm_tc<<<(NN + 127) / 128, 256>>>(W);
        k_agg<<<(NN * 32 + 255) / 256, 256>>>(b, gam + l * HH, bet + l * HH,
                                              mean + l * HH, var + l * HH, 1);
    }

    // fused pooling + head
    k_pool_mlp<<<GG, 128>>>(l1w, l1b, l2w, l2b, out);
}

// round 10
// speedup vs baseline: 1.6341x; 1.1793x over previous
#include <cuda_runtime.h>
#include <cuda_bf16.h>

#define NN 50000
#define EE 600000
#define HH 128
#define GG 2048
#define FIN 11
#define LL 5
#define EPSV 1e-5f
#define SCAN_B 49   // ceil(NN/1024)

// ---------------- scratch (static device globals) ----------------
__device__ float        g_dinv[NN];
__device__ int          g_cnt[NN];
__device__ int          g_off[NN + 1];
__device__ int          g_cur[NN];
__device__ int2         g_csr[EE];            // {src, nrm-bits}
__device__ float4       g_h[NN * (HH / 4)];   // h fp32 (self term)
__device__ unsigned int g_hb[NN * (HH / 2)];  // h bf16x2 (neighbor gathers), [N][64]
__device__ float4       g_x[NN * (HH / 4)];   // post-agg features
__device__ int          g_start[GG + 1];
__device__ int          g_part[64];
__device__ int          g_pscan[64];

// ---------------- bf16 helpers ----------------
__device__ __forceinline__ unsigned packbf2(float a, float b) {
    unsigned r;
    asm("cvt.rn.bf16x2.f32 %0, %1, %2;" : "=r"(r) : "f"(b), "f"(a));
    return r;  // low half = a, high half = b
}
// split two floats into hi (bf16x2) and lo (bf16x2 of residuals)
__device__ __forceinline__ void bfsplit2(float a, float b, unsigned& hi, unsigned& lo) {
    hi = packbf2(a, b);
    float ra = a - __uint_as_float(hi << 16);
    float rb = b - __uint_as_float(hi & 0xFFFF0000u);
    lo = packbf2(ra, rb);
}
__device__ __forceinline__ void mma_bf16(float* d, const unsigned* a, const unsigned* b) {
    asm volatile(
        "mma.sync.aligned.m16n8k16.row.col.f32.bf16.bf16.f32 "
        "{%0,%1,%2,%3}, {%4,%5,%6,%7}, {%8,%9}, {%0,%1,%2,%3};"
        : "+f"(d[0]), "+f"(d[1]), "+f"(d[2]), "+f"(d[3])
        : "r"(a[0]), "r"(a[1]), "r"(a[2]), "r"(a[3]), "r"(b[0]), "r"(b[1]));
}

// ---------------- degree / CSR build ----------------
__global__ void k_zero_cnt() {
    int i = blockIdx.x * blockDim.x + threadIdx.x;
    if (i < NN) g_cnt[i] = 0;
}

__global__ void k_count(const int* __restrict__ ei) {
    int e = blockIdx.x * blockDim.x + threadIdx.x;
    if (e < EE) atomicAdd(&g_cnt[ei[EE + e]], 1);
}

// ---- coalesced 3-phase scan (phase 1 also computes dinv) ----
__global__ void k_scan1() {
    int t = threadIdx.x, b = blockIdx.x;
    int i = b * 1024 + t;
    int v = (i < NN) ? g_cnt[i] : 0;
    if (i < NN) g_dinv[i] = rsqrtf((float)v + 1.0f);   // +1 self-loop
    int lane = t & 31, wid = t >> 5;
    int x = v;
    #pragma unroll
    for (int d = 1; d < 32; d <<= 1) {
        int n = __shfl_up_sync(0xFFFFFFFF, x, d);
        if (lane >= d) x += n;
    }
    __shared__ int ws[32];
    if (lane == 31) ws[wid] = x;
    __syncthreads();
    if (wid == 0) {
        int w = ws[lane];
        #pragma unroll
        for (int d = 1; d < 32; d <<= 1) {
            int n = __shfl_up_sync(0xFFFFFFFF, w, d);
            if (lane >= d) w += n;
        }
        ws[lane] = w;
    }
    __syncthreads();
    int incl = x + (wid ? ws[wid - 1] : 0);
    if (i < NN) g_off[i] = incl - v;
    if (t == 1023) g_part[b] = incl;
}

__global__ void k_scan2() {
    int lane = threadIdx.x;   // 32
    int a0 = (2 * lane     < SCAN_B) ? g_part[2 * lane]     : 0;
    int a1 = (2 * lane + 1 < SCAN_B) ? g_part[2 * lane + 1] : 0;
    int s = a0 + a1;
    int x = s;
    #pragma unroll
    for (int d = 1; d < 32; d <<= 1) {
        int n = __shfl_up_sync(0xFFFFFFFF, x, d);
        if (lane >= d) x += n;
    }
    int excl = x - s;
    if (2 * lane     < SCAN_B) g_pscan[2 * lane]     = excl;
    if (2 * lane + 1 < SCAN_B) g_pscan[2 * lane + 1] = excl + a0;
    if (lane == 31) g_off[NN] = x;
}

// phase 3 + per-graph boundaries (batch is sorted)
__global__ void k_scan3(const int* __restrict__ batch) {
    int i = blockIdx.x * blockDim.x + threadIdx.x;
    if (i >= NN) return;
    int o = g_off[i] + g_pscan[i >> 10];
    g_off[i] = o;
    g_cur[i] = o;
    int b = batch[i];
    if (i == 0) {
        for (int g = 0; g <= b; g++) g_start[g] = 0;
    } else {
        int pb = batch[i - 1];
        for (int g = pb + 1; g <= b; g++) g_start[g] = i;
    }
    if (i == NN - 1) {
        for (int g = b + 1; g <= GG; g++) g_start[g] = NN;
    }
}

__global__ void k_fill(const int* __restrict__ ei) {
    int e = blockIdx.x * blockDim.x + threadIdx.x;
    if (e < EE) {
        int s = ei[e];
        int d = ei[EE + e];
        int p = atomicAdd(&g_cur[d], 1);
        g_csr[p] = make_int2(s, __float_as_int(g_dinv[s] * g_dinv[d]));
    }
}

// ---------------- GEMM: layer 0 (K = 11), writes g_h + g_hb ----------------
__global__ void k_gemm0(const float* __restrict__ X, const float* __restrict__ W0) {
    __shared__ float sW[FIN * HH];
    __shared__ float sx[16 * FIN];
    int t = threadIdx.x;
    int rowBase = blockIdx.x * 16;
    for (int idx = t; idx < FIN * HH; idx += 256) sW[idx] = W0[idx];
    if (t < 16 * FIN) {
        int r = rowBase + t / FIN;
        sx[t] = (r < NN) ? X[r * FIN + (t % FIN)] : 0.0f;
    }
    __syncthreads();
    int c = t & 127;
    int rh = t >> 7;
    float w[FIN];
    #pragma unroll
    for (int k = 0; k < FIN; k++) w[k] = sW[k * HH + c];
    float* hout = (float*)g_h;
    #pragma unroll
    for (int i = 0; i < 8; i++) {
        int rloc = rh + 2 * i;
        int r = rowBase + rloc;
        if (r < NN) {
            float acc = 0.0f;
            #pragma unroll
            for (int k = 0; k < FIN; k++) acc += sx[rloc * FIN + k] * w[k];
            hout[r * HH + c] = acc;
            float other = __shfl_xor_sync(0xFFFFFFFF, acc, 1);
            if ((c & 1) == 0)
                g_hb[r * 64 + (c >> 1)] = packbf2(acc, other);
        }
    }
}

// ---------------- GEMM 128x128, 2-term bf16 split (m16n8k16): g_x @ W -> g_h + g_hb ----
// K chunked by 32 (16 k2-words). smem holds bf16x2-packed hi/lo for A and B.
__global__ void __launch_bounds__(256) k_gemm_tc(const float* __restrict__ W) {
    __shared__ unsigned sAh[128][20], sAl[128][20];   // [row][k2] pitch 20
    __shared__ unsigned sBh[16][136], sBl[16][136];   // [k2][n]  pitch 136
    int t = threadIdx.x;
    int rowBase = blockIdx.x * 128;
    int lane = t & 31, w = t >> 5;
    int wm = w >> 1, wn = w & 1;
    int gq = lane >> 2, cq = lane & 3;

    float acc[2][8][4];
    #pragma unroll
    for (int mt = 0; mt < 2; mt++)
        #pragma unroll
        for (int nt = 0; nt < 8; nt++)
            #pragma unroll
            for (int k = 0; k < 4; k++) acc[mt][nt][k] = 0.0f;

    const float4* W4 = (const float4*)W;

    for (int kc = 0; kc < 4; kc++) {
        // A: 128 rows x 32 k = 1024 float4; pack pairs along k (k2 = c4*2, c4*2+1)
        #pragma unroll
        for (int i = 0; i < 4; i++) {
            int idx = t + 256 * i;             // 0..1023
            int r = idx >> 3, c4 = idx & 7;    // 8 float4 per row
            int gr = rowBase + r;
            float4 v = (gr < NN) ? g_x[gr * 32 + kc * 8 + c4]
                                 : make_float4(0.f, 0.f, 0.f, 0.f);
            unsigned h0, l0, h1, l1;
            bfsplit2(v.x, v.y, h0, l0);
            bfsplit2(v.z, v.w, h1, l1);
            int k2 = c4 * 2;
            *(uint2*)&sAh[r][k2] = make_uint2(h0, h1);
            *(uint2*)&sAl[r][k2] = make_uint2(l0, l1);
        }
        // B: 32 k x 128 n; each thread packs one (k2, n4) pair along k
        #pragma unroll
        for (int i = 0; i < 2; i++) {
            int idx = t + 256 * i;             // 0..511
            int k2 = idx >> 5, n4 = idx & 31;  // k2 0..15
            int kr0 = kc * 32 + k2 * 2;
            float4 v0 = W4[kr0 * 32 + n4];
            float4 v1 = W4[(kr0 + 1) * 32 + n4];
            unsigned h0, l0, h1, l1, h2, l2, h3, l3;
            bfsplit2(v0.x, v1.x, h0, l0);
            bfsplit2(v0.y, v1.y, h1, l1);
            bfsplit2(v0.z, v1.z, h2, l2);
            bfsplit2(v0.w, v1.w, h3, l3);
            int nb = n4 * 4;
            *(uint4*)&sBh[k2][nb] = make_uint4(h0, h1, h2, h3);
            *(uint4*)&sBl[k2][nb] = make_uint4(l0, l1, l2, l3);
        }
        __syncthreads();

        #pragma unroll
        for (int ks = 0; ks < 2; ks++) {
            int kb2 = ks * 8;                  // k2 base of this k16 step
            unsigned bh[8][2], bl[8][2];
            #pragma unroll
            for (int nt = 0; nt < 8; nt++) {
                int n0 = wn * 64 + nt * 8 + gq;
                bh[nt][0] = sBh[kb2 + cq][n0];
                bh[nt][1] = sBh[kb2 + 4 + cq][n0];
                bl[nt][0] = sBl[kb2 + cq][n0];
                bl[nt][1] = sBl[kb2 + 4 + cq][n0];
            }
            unsigned ah[2][4], al[2][4];
            #pragma unroll
            for (int mt = 0; mt < 2; mt++) {
                int r0 = wm * 32 + mt * 16 + gq;
                ah[mt][0] = sAh[r0][kb2 + cq];
                ah[mt][1] = sAh[r0 + 8][kb2 + cq];
                ah[mt][2] = sAh[r0][kb2 + 4 + cq];
                ah[mt][3] = sAh[r0 + 8][kb2 + 4 + cq];
                al[mt][0] = sAl[r0][kb2 + cq];
                al[mt][1] = sAl[r0 + 8][kb2 + cq];
                al[mt][2] = sAl[r0][kb2 + 4 + cq];
                al[mt][3] = sAl[r0 + 8][kb2 + 4 + cq];
            }
            #pragma unroll
            for (int mt = 0; mt < 2; mt++)
                #pragma unroll
                for (int nt = 0; nt < 8; nt++) {
                    mma_bf16(acc[mt][nt], ah[mt], bh[nt]);
                    mma_bf16(acc[mt][nt], ah[mt], bl[nt]);
                    mma_bf16(acc[mt][nt], al[mt], bh[nt]);
                }
        }
        __syncthreads();
    }

    // epilogue: write g_h (fp32) + g_hb (bf16x2)
    float* hf = (float*)g_h;
    #pragma unroll
    for (int mt = 0; mt < 2; mt++) {
        int r0 = rowBase + wm * 32 + mt * 16 + gq;
        #pragma unroll
        for (int nt = 0; nt < 8; nt++) {
            int col = wn * 64 + nt * 8 + cq * 2;
            if (r0 < NN) {
                *(float2*)&hf[r0 * HH + col] = make_float2(acc[mt][nt][0], acc[mt][nt][1]);
                g_hb[r0 * 64 + (col >> 1)] = packbf2(acc[mt][nt][0], acc[mt][nt][1]);
            }
            if (r0 + 8 < NN) {
                *(float2*)&hf[(r0 + 8) * HH + col] = make_float2(acc[mt][nt][2], acc[mt][nt][3]);
                g_hb[(r0 + 8) * 64 + (col >> 1)] = packbf2(acc[mt][nt][2], acc[mt][nt][3]);
            }
        }
    }
}

// ---------------- aggregation (bf16 gathers, 4x unrolled) + bias + BN + ReLU + residual ----
__device__ __forceinline__ void bf2fma(float4& acc, float w, uint2 pb) {
    acc.x += w * __uint_as_float(pb.x << 16);
    acc.y += w * __uint_as_float(pb.x & 0xFFFF0000u);
    acc.z += w * __uint_as_float(pb.y << 16);
    acc.w += w * __uint_as_float(pb.y & 0xFFFF0000u);
}

__global__ void k_agg(const float* __restrict__ bvec,
                      const float* __restrict__ gamma, const float* __restrict__ beta,
                      const float* __restrict__ mean,  const float* __restrict__ var,
                      int residual) {
    int gwarp = (blockIdx.x * blockDim.x + threadIdx.x) >> 5;
    if (gwarp >= NN) return;
    int lane = threadIdx.x & 31;
    int i = gwarp;

    float di = g_dinv[i];
    float self = di * di;
    float4 hv = g_h[i * 32 + lane];     // exact fp32 self term
    float4 acc = make_float4(hv.x * self, hv.y * self, hv.z * self, hv.w * self);

    int s0 = g_off[i], s1 = g_off[i + 1];
    int e = s0;
    const unsigned* hb = g_hb;
    for (; e + 4 <= s1; e += 4) {
        int2 sa = g_csr[e];
        int2 sb = g_csr[e + 1];
        int2 sc = g_csr[e + 2];
        int2 sd = g_csr[e + 3];
        uint2 pa = *(const uint2*)&hb[sa.x * 64 + 2 * lane];
        uint2 pb = *(const uint2*)&hb[sb.x * 64 + 2 * lane];
        uint2 pc = *(const uint2*)&hb[sc.x * 64 + 2 * lane];
        uint2 pd = *(const uint2*)&hb[sd.x * 64 + 2 * lane];
        bf2fma(acc, __int_as_float(sa.y), pa);
        bf2fma(acc, __int_as_float(sb.y), pb);
        bf2fma(acc, __int_as_float(sc.y), pc);
        bf2fma(acc, __int_as_float(sd.y), pd);
    }
    for (; e < s1; e++) {
        int2 se = g_csr[e];
        uint2 pe = *(const uint2*)&hb[se.x * 64 + 2 * lane];
        bf2fma(acc, __int_as_float(se.y), pe);
    }

    int c0 = 4 * lane;
    float b0v = bvec[c0],  b1v = bvec[c0 + 1], b2v = bvec[c0 + 2], b3v = bvec[c0 + 3];
    float g0 = gamma[c0],  g1 = gamma[c0 + 1], g2 = gamma[c0 + 2], g3 = gamma[c0 + 3];
    float t0 = beta[c0],   t1 = beta[c0 + 1],  t2 = beta[c0 + 2],  t3 = beta[c0 + 3];
    float m0 = mean[c0],   m1 = mean[c0 + 1],  m2 = mean[c0 + 2],  m3 = mean[c0 + 3];
    float v0 = var[c0],    v1 = var[c0 + 1],   v2 = var[c0 + 2],   v3 = var[c0 + 3];

    float s0c = g0 * rsqrtf(v0 + EPSV), s1c = g1 * rsqrtf(v1 + EPSV);
    float s2c = g2 * rsqrtf(v2 + EPSV), s3c = g3 * rsqrtf(v3 + EPSV);

    float4 r;
    r.x = fmaxf((acc.x + b0v - m0) * s0c + t0, 0.0f);
    r.y = fmaxf((acc.y + b1v - m1) * s1c + t1, 0.0f);
    r.z = fmaxf((acc.z + b2v - m2) * s2c + t2, 0.0f);
    r.w = fmaxf((acc.w + b3v - m3) * s3c + t3, 0.0f);

    if (residual) {
        float4 xp = g_x[i * 32 + lane];
        r.x += xp.x; r.y += xp.y; r.z += xp.z; r.w += xp.w;
    }
    g_x[i * 32 + lane] = r;
}

// ---------------- fused pooling + MLP head (block per graph) ----------------
__global__ void k_pool_mlp(const float* __restrict__ l1w, const float* __restrict__ l1b,
                           const float* __restrict__ l2w, const float* __restrict__ l2b,
                           float* __restrict__ out) {
    int g = blockIdx.x;
    int t = threadIdx.x;  // 128
    __shared__ float sp[HH];
    __shared__ float red[64];

    int s = g_start[g], e = g_start[g + 1];
    const float* xf = (const float*)g_x;
    float sum = 0.0f;
    for (int r = s; r < e; r++) sum += xf[r * HH + t];
    float inv = 1.0f / fmaxf((float)(e - s), 1.0f);
    sp[t] = sum * inv;
    __syncthreads();

    if (t < 64) {
        float acc = l1b[t];
        #pragma unroll 8
        for (int k = 0; k < HH; k++) acc += sp[k] * l1w[k * 64 + t];
        float h1 = fmaxf(acc, 0.0f);
        red[t] = h1 * l2w[t];
    }
    __syncthreads();
    if (t < 32) {
        float v = red[t] + red[t + 32];
        #pragma unroll
        for (int d = 16; d > 0; d >>= 1) v += __shfl_down_sync(0xFFFFFFFF, v, d);
        if (t == 0) out[g] = v + l2b[0];
    }
}

// ---------------- launch ----------------
extern "C" void kernel_launch(void* const* d_in, const int* in_sizes, int n_in,
                              void* d_out, int out_size) {
    const float* x     = (const float*)d_in[0];
    const int*   ei    = (const int*)d_in[1];
    const int*   batch = (const int*)d_in[2];
    const float* W0    = (const float*)d_in[3];
    const float* b0    = (const float*)d_in[4];
    const float* Ws    = (const float*)d_in[5];
    const float* bs    = (const float*)d_in[6];
    const float* gam   = (const float*)d_in[7];
    const float* bet   = (const float*)d_in[8];
    const float* mean  = (const float*)d_in[9];
    const float* var   = (const float*)d_in[10];
    const float* l1w   = (const float*)d_in[11];
    const float* l1b   = (const float*)d_in[12];
    const float* l2w   = (const float*)d_in[13];
    const float* l2b   = (const float*)d_in[14];
    float* out = (float*)d_out;

    // graph prep
    k_zero_cnt<<<(NN + 255) / 256, 256>>>();
    k_count<<<(EE + 255) / 256, 256>>>(ei);
    k_scan1<<<SCAN_B, 1024>>>();
    k_scan2<<<1, 32>>>();
    k_scan3<<<(NN + 255) / 256, 256>>>(batch);
    k_fill<<<(EE + 255) / 256, 256>>>(ei);

    // layer 0
    k_gemm0<<<(NN + 15) / 16, 256>>>(x, W0);
    k_agg<<<(NN * 32 + 255) / 256, 256>>>(b0, gam, bet, mean, var, 0);

    // layers 1..4 (bf16 split tensor-core GEMM)
    for (int l = 1; l < LL; l++) {
        const float* W = Ws + (l - 1) * HH * HH;
        const float* b = bs + (l - 1) * HH;
        k_gemm_tc<<<(NN + 127) / 128, 256>>>(W);
        k_agg<<<(NN * 32 + 255) / 256, 256>>>(b, gam + l * HH, bet + l * HH,
                                              mean + l * HH, var + l * HH, 1);
    }

    // fused pooling + head
    k_pool_mlp<<<GG, 128>>>(l1w, l1b, l2w, l2b, out);
}

// round 11
// speedup vs baseline: 2.0567x; 1.2586x over previous
#include <cuda_runtime.h>
#include <cuda_bf16.h>

#define NN 50000
#define EE 600000
#define HH 128
#define GG 2048
#define FIN 11
#define LL 5
#define EPSV 1e-5f
#define SCAN_B 49   // ceil(NN/1024)

// ---------------- scratch (static device globals) ----------------
__device__ float        g_dinv[NN];
__device__ int          g_cnt[NN];
__device__ int          g_off[NN + 1];
__device__ int          g_cur[NN];
__device__ int2         g_csr[EE];            // {src, nrm-bits}
__device__ unsigned int g_hb[NN * (HH / 2)];  // h bf16x2, [N][64]
__device__ float4       g_x[NN * (HH / 4)];   // post-agg features (fp32)
__device__ int          g_start[GG + 1];
__device__ int          g_part[64];
__device__ int          g_pscan[64];

// ---------------- bf16 helpers ----------------
__device__ __forceinline__ unsigned packbf2(float a, float b) {
    unsigned r;
    asm("cvt.rn.bf16x2.f32 %0, %1, %2;" : "=r"(r) : "f"(b), "f"(a));
    return r;  // low half = a, high half = b
}
__device__ __forceinline__ void bfsplit2(float a, float b, unsigned& hi, unsigned& lo) {
    hi = packbf2(a, b);
    float ra = a - __uint_as_float(hi << 16);
    float rb = b - __uint_as_float(hi & 0xFFFF0000u);
    lo = packbf2(ra, rb);
}
__device__ __forceinline__ void mma_bf16(float* d, const unsigned* a, const unsigned* b) {
    asm volatile(
        "mma.sync.aligned.m16n8k16.row.col.f32.bf16.bf16.f32 "
        "{%0,%1,%2,%3}, {%4,%5,%6,%7}, {%8,%9}, {%0,%1,%2,%3};"
        : "+f"(d[0]), "+f"(d[1]), "+f"(d[2]), "+f"(d[3])
        : "r"(a[0]), "r"(a[1]), "r"(a[2]), "r"(a[3]), "r"(b[0]), "r"(b[1]));
}

// ---------------- degree / CSR build ----------------
__global__ void k_zero_cnt() {
    int i = blockIdx.x * blockDim.x + threadIdx.x;
    if (i < NN) g_cnt[i] = 0;
}

__global__ void k_count(const int* __restrict__ ei) {
    int e = blockIdx.x * blockDim.x + threadIdx.x;
    if (e < EE) atomicAdd(&g_cnt[ei[EE + e]], 1);
}

// ---- coalesced 3-phase scan (phase 1 also computes dinv) ----
__global__ void k_scan1() {
    int t = threadIdx.x, b = blockIdx.x;
    int i = b * 1024 + t;
    int v = (i < NN) ? g_cnt[i] : 0;
    if (i < NN) g_dinv[i] = rsqrtf((float)v + 1.0f);   // +1 self-loop
    int lane = t & 31, wid = t >> 5;
    int x = v;
    #pragma unroll
    for (int d = 1; d < 32; d <<= 1) {
        int n = __shfl_up_sync(0xFFFFFFFF, x, d);
        if (lane >= d) x += n;
    }
    __shared__ int ws[32];
    if (lane == 31) ws[wid] = x;
    __syncthreads();
    if (wid == 0) {
        int w = ws[lane];
        #pragma unroll
        for (int d = 1; d < 32; d <<= 1) {
            int n = __shfl_up_sync(0xFFFFFFFF, w, d);
            if (lane >= d) w += n;
        }
        ws[lane] = w;
    }
    __syncthreads();
    int incl = x + (wid ? ws[wid - 1] : 0);
    if (i < NN) g_off[i] = incl - v;
    if (t == 1023) g_part[b] = incl;
}

__global__ void k_scan2() {
    int lane = threadIdx.x;   // 32
    int a0 = (2 * lane     < SCAN_B) ? g_part[2 * lane]     : 0;
    int a1 = (2 * lane + 1 < SCAN_B) ? g_part[2 * lane + 1] : 0;
    int s = a0 + a1;
    int x = s;
    #pragma unroll
    for (int d = 1; d < 32; d <<= 1) {
        int n = __shfl_up_sync(0xFFFFFFFF, x, d);
        if (lane >= d) x += n;
    }
    int excl = x - s;
    if (2 * lane     < SCAN_B) g_pscan[2 * lane]     = excl;
    if (2 * lane + 1 < SCAN_B) g_pscan[2 * lane + 1] = excl + a0;
    if (lane == 31) g_off[NN] = x;
}

// phase 3 + per-graph boundaries (batch is sorted)
__global__ void k_scan3(const int* __restrict__ batch) {
    int i = blockIdx.x * blockDim.x + threadIdx.x;
    if (i >= NN) return;
    int o = g_off[i] + g_pscan[i >> 10];
    g_off[i] = o;
    g_cur[i] = o;
    int b = batch[i];
    if (i == 0) {
        for (int g = 0; g <= b; g++) g_start[g] = 0;
    } else {
        int pb = batch[i - 1];
        for (int g = pb + 1; g <= b; g++) g_start[g] = i;
    }
    if (i == NN - 1) {
        for (int g = b + 1; g <= GG; g++) g_start[g] = NN;
    }
}

__global__ void k_fill(const int* __restrict__ ei) {
    int e = blockIdx.x * blockDim.x + threadIdx.x;
    if (e < EE) {
        int s = ei[e];
        int d = ei[EE + e];
        int p = atomicAdd(&g_cur[d], 1);
        g_csr[p] = make_int2(s, __float_as_int(g_dinv[s] * g_dinv[d]));
    }
}

// ---------------- GEMM: layer 0 (K = 11), writes g_hb ----------------
__global__ void k_gemm0(const float* __restrict__ X, const float* __restrict__ W0) {
    __shared__ float sW[FIN * HH];
    __shared__ float sx[16 * FIN];
    int t = threadIdx.x;
    int rowBase = blockIdx.x * 16;
    for (int idx = t; idx < FIN * HH; idx += 256) sW[idx] = W0[idx];
    if (t < 16 * FIN) {
        int r = rowBase + t / FIN;
        sx[t] = (r < NN) ? X[r * FIN + (t % FIN)] : 0.0f;
    }
    __syncthreads();
    int c = t & 127;
    int rh = t >> 7;
    float w[FIN];
    #pragma unroll
    for (int k = 0; k < FIN; k++) w[k] = sW[k * HH + c];
    #pragma unroll
    for (int i = 0; i < 8; i++) {
        int rloc = rh + 2 * i;
        int r = rowBase + rloc;
        if (r < NN) {
            float acc = 0.0f;
            #pragma unroll
            for (int k = 0; k < FIN; k++) acc += sx[rloc * FIN + k] * w[k];
            float other = __shfl_xor_sync(0xFFFFFFFF, acc, 1);
            if ((c & 1) == 0)
                g_hb[r * 64 + (c >> 1)] = packbf2(acc, other);
        }
    }
}

// ---------------- GEMM 128x128, 2-term bf16 (A single-bf16, B hi/lo split) ----------
// g_x @ W -> g_hb.  K chunked by 32 (16 bf16x2 words).
__global__ void __launch_bounds__(256) k_gemm_tc(const float* __restrict__ W) {
    __shared__ unsigned sA[128][20];                  // [row][k2] pitch 20
    __shared__ unsigned sBh[16][136], sBl[16][136];   // [k2][n]  pitch 136
    int t = threadIdx.x;
    int rowBase = blockIdx.x * 128;
    int lane = t & 31, w = t >> 5;
    int wm = w >> 1, wn = w & 1;
    int gq = lane >> 2, cq = lane & 3;

    float acc[2][8][4];
    #pragma unroll
    for (int mt = 0; mt < 2; mt++)
        #pragma unroll
        for (int nt = 0; nt < 8; nt++)
            #pragma unroll
            for (int k = 0; k < 4; k++) acc[mt][nt][k] = 0.0f;

    const float4* W4 = (const float4*)W;

    for (int kc = 0; kc < 4; kc++) {
        // A: 128 rows x 32 k = 1024 float4; single bf16 round, packed along k
        #pragma unroll
        for (int i = 0; i < 4; i++) {
            int idx = t + 256 * i;             // 0..1023
            int r = idx >> 3, c4 = idx & 7;
            int gr = rowBase + r;
            float4 v = (gr < NN) ? g_x[gr * 32 + kc * 8 + c4]
                                 : make_float4(0.f, 0.f, 0.f, 0.f);
            unsigned p0 = packbf2(v.x, v.y);
            unsigned p1 = packbf2(v.z, v.w);
            *(uint2*)&sA[r][c4 * 2] = make_uint2(p0, p1);
        }
        // B: 32 k x 128 n; hi/lo split, packed along k
        #pragma unroll
        for (int i = 0; i < 2; i++) {
            int idx = t + 256 * i;             // 0..511
            int k2 = idx >> 5, n4 = idx & 31;  // k2 0..15
            int kr0 = kc * 32 + k2 * 2;
            float4 v0 = W4[kr0 * 32 + n4];
            float4 v1 = W4[(kr0 + 1) * 32 + n4];
            unsigned h0, l0, h1, l1, h2, l2, h3, l3;
            bfsplit2(v0.x, v1.x, h0, l0);
            bfsplit2(v0.y, v1.y, h1, l1);
            bfsplit2(v0.z, v1.z, h2, l2);
            bfsplit2(v0.w, v1.w, h3, l3);
            int nb = n4 * 4;
            *(uint4*)&sBh[k2][nb] = make_uint4(h0, h1, h2, h3);
            *(uint4*)&sBl[k2][nb] = make_uint4(l0, l1, l2, l3);
        }
        __syncthreads();

        #pragma unroll
        for (int ks = 0; ks < 2; ks++) {
            int kb2 = ks * 8;
            unsigned bh[8][2], bl[8][2];
            #pragma unroll
            for (int nt = 0; nt < 8; nt++) {
                int n0 = wn * 64 + nt * 8 + gq;
                bh[nt][0] = sBh[kb2 + cq][n0];
                bh[nt][1] = sBh[kb2 + 4 + cq][n0];
                bl[nt][0] = sBl[kb2 + cq][n0];
                bl[nt][1] = sBl[kb2 + 4 + cq][n0];
            }
            unsigned ah[2][4];
            #pragma unroll
            for (int mt = 0; mt < 2; mt++) {
                int r0 = wm * 32 + mt * 16 + gq;
                ah[mt][0] = sA[r0][kb2 + cq];
                ah[mt][1] = sA[r0 + 8][kb2 + cq];
                ah[mt][2] = sA[r0][kb2 + 4 + cq];
                ah[mt][3] = sA[r0 + 8][kb2 + 4 + cq];
            }
            #pragma unroll
            for (int mt = 0; mt < 2; mt++)
                #pragma unroll
                for (int nt = 0; nt < 8; nt++) {
                    mma_bf16(acc[mt][nt], ah[mt], bh[nt]);
                    mma_bf16(acc[mt][nt], ah[mt], bl[nt]);
                }
        }
        __syncthreads();
    }

    // epilogue: write g_hb only (bf16x2)
    #pragma unroll
    for (int mt = 0; mt < 2; mt++) {
        int r0 = rowBase + wm * 32 + mt * 16 + gq;
        #pragma unroll
        for (int nt = 0; nt < 8; nt++) {
            int col = wn * 64 + nt * 8 + cq * 2;
            if (r0 < NN)
                g_hb[r0 * 64 + (col >> 1)] = packbf2(acc[mt][nt][0], acc[mt][nt][1]);
            if (r0 + 8 < NN)
                g_hb[(r0 + 8) * 64 + (col >> 1)] = packbf2(acc[mt][nt][2], acc[mt][nt][3]);
        }
    }
}

// ---------------- aggregation: half-warp (16 lanes) per node, uint4 gathers ----------
__device__ __forceinline__ void bf8fma(float* acc, float w, uint4 p) {
    acc[0] += w * __uint_as_float(p.x << 16);
    acc[1] += w * __uint_as_float(p.x & 0xFFFF0000u);
    acc[2] += w * __uint_as_float(p.y << 16);
    acc[3] += w * __uint_as_float(p.y & 0xFFFF0000u);
    acc[4] += w * __uint_as_float(p.z << 16);
    acc[5] += w * __uint_as_float(p.z & 0xFFFF0000u);
    acc[6] += w * __uint_as_float(p.w << 16);
    acc[7] += w * __uint_as_float(p.w & 0xFFFF0000u);
}

__global__ void k_agg(const float* __restrict__ bvec,
                      const float* __restrict__ gamma, const float* __restrict__ beta,
                      const float* __restrict__ mean,  const float* __restrict__ var,
                      int residual) {
    int idx = blockIdx.x * blockDim.x + threadIdx.x;
    int node = idx >> 4;
    if (node >= NN) return;
    int l16 = threadIdx.x & 15;
    const uint4* hb4 = (const uint4*)g_hb;   // [N][16] uint4

    float di = g_dinv[node];
    float self = di * di;
    float acc[8] = {0, 0, 0, 0, 0, 0, 0, 0};
    bf8fma(acc, self, hb4[node * 16 + l16]);

    int s0 = g_off[node], s1 = g_off[node + 1];
    int e = s0;
    for (; e + 2 <= s1; e += 2) {
        int2 sa = g_csr[e];
        int2 sb = g_csr[e + 1];
        uint4 pa = hb4[sa.x * 16 + l16];
        uint4 pb = hb4[sb.x * 16 + l16];
        bf8fma(acc, __int_as_float(sa.y), pa);
        bf8fma(acc, __int_as_float(sb.y), pb);
    }
    if (e < s1) {
        int2 se = g_csr[e];
        bf8fma(acc, __int_as_float(se.y), hb4[se.x * 16 + l16]);
    }

    int c0 = 8 * l16;
    float4 bv0 = *(const float4*)&bvec[c0],  bv1 = *(const float4*)&bvec[c0 + 4];
    float4 gm0 = *(const float4*)&gamma[c0], gm1 = *(const float4*)&gamma[c0 + 4];
    float4 bt0 = *(const float4*)&beta[c0],  bt1 = *(const float4*)&beta[c0 + 4];
    float4 mn0 = *(const float4*)&mean[c0],  mn1 = *(const float4*)&mean[c0 + 4];
    float4 vr0 = *(const float4*)&var[c0],   vr1 = *(const float4*)&var[c0 + 4];

    float b8[8]  = {bv0.x, bv0.y, bv0.z, bv0.w, bv1.x, bv1.y, bv1.z, bv1.w};
    float g8[8]  = {gm0.x, gm0.y, gm0.z, gm0.w, gm1.x, gm1.y, gm1.z, gm1.w};
    float t8[8]  = {bt0.x, bt0.y, bt0.z, bt0.w, bt1.x, bt1.y, bt1.z, bt1.w};
    float m8[8]  = {mn0.x, mn0.y, mn0.z, mn0.w, mn1.x, mn1.y, mn1.z, mn1.w};
    float v8[8]  = {vr0.x, vr0.y, vr0.z, vr0.w, vr1.x, vr1.y, vr1.z, vr1.w};

    float r8[8];
    #pragma unroll
    for (int j = 0; j < 8; j++) {
        float sc = g8[j] * rsqrtf(v8[j] + EPSV);
        r8[j] = fmaxf((acc[j] + b8[j] - m8[j]) * sc + t8[j], 0.0f);
    }

    if (residual) {
        float4 x0 = g_x[node * 32 + 2 * l16];
        float4 x1 = g_x[node * 32 + 2 * l16 + 1];
        r8[0] += x0.x; r8[1] += x0.y; r8[2] += x0.z; r8[3] += x0.w;
        r8[4] += x1.x; r8[5] += x1.y; r8[6] += x1.z; r8[7] += x1.w;
    }
    g_x[node * 32 + 2 * l16]     = make_float4(r8[0], r8[1], r8[2], r8[3]);
    g_x[node * 32 + 2 * l16 + 1] = make_float4(r8[4], r8[5], r8[6], r8[7]);
}

// ---------------- fused pooling + MLP head (block per graph) ----------------
__global__ void k_pool_mlp(const float* __restrict__ l1w, const float* __restrict__ l1b,
                           const float* __restrict__ l2w, const float* __restrict__ l2b,
                           float* __restrict__ out) {
    int g = blockIdx.x;
    int t = threadIdx.x;  // 128
    __shared__ float sp[HH];
    __shared__ float red[64];

    int s = g_start[g], e = g_start[g + 1];
    const float* xf = (const float*)g_x;
    float sum = 0.0f;
    for (int r = s; r < e; r++) sum += xf[r * HH + t];
    float inv = 1.0f / fmaxf((float)(e - s), 1.0f);
    sp[t] = sum * inv;
    __syncthreads();

    if (t < 64) {
        float acc = l1b[t];
        #pragma unroll 8
        for (int k = 0; k < HH; k++) acc += sp[k] * l1w[k * 64 + t];
        float h1 = fmaxf(acc, 0.0f);
        red[t] = h1 * l2w[t];
    }
    __syncthreads();
    if (t < 32) {
        float v = red[t] + red[t + 32];
        #pragma unroll
        for (int d = 16; d > 0; d >>= 1) v += __shfl_down_sync(0xFFFFFFFF, v, d);
        if (t == 0) out[g] = v + l2b[0];
    }
}

// ---------------- launch ----------------
extern "C" void kernel_launch(void* const* d_in, const int* in_sizes, int n_in,
                              void* d_out, int out_size) {
    const float* x     = (const float*)d_in[0];
    const int*   ei    = (const int*)d_in[1];
    const int*   batch = (const int*)d_in[2];
    const float* W0    = (const float*)d_in[3];
    const float* b0    = (const float*)d_in[4];
    const float* Ws    = (const float*)d_in[5];
    const float* bs    = (const float*)d_in[6];
    const float* gam   = (const float*)d_in[7];
    const float* bet   = (const float*)d_in[8];
    const float* mean  = (const float*)d_in[9];
    const float* var   = (const float*)d_in[10];
    const float* l1w   = (const float*)d_in[11];
    const float* l1b   = (const float*)d_in[12];
    const float* l2w   = (const float*)d_in[13];
    const float* l2b   = (const float*)d_in[14];
    float* out = (float*)d_out;

    // graph prep
    k_zero_cnt<<<(NN + 255) / 256, 256>>>();
    k_count<<<(EE + 255) / 256, 256>>>(ei);
    k_scan1<<<SCAN_B, 1024>>>();
    k_scan2<<<1, 32>>>();
    k_scan3<<<(NN + 255) / 256, 256>>>(batch);
    k_fill<<<(EE + 255) / 256, 256>>>(ei);

    // layer 0
    k_gemm0<<<(NN + 15) / 16, 256>>>(x, W0);
    k_agg<<<(NN * 16 + 255) / 256, 256>>>(b0, gam, bet, mean, var, 0);

    // layers 1..4 (bf16 2-term tensor-core GEMM)
    for (int l = 1; l < LL; l++) {
        const float* W = Ws + (l - 1) * HH * HH;
        const float* b = bs + (l - 1) * HH;
        k_gemm_tc<<<(NN + 127) / 128, 256>>>(W);
        k_agg<<<(NN * 16 + 255) / 256, 256>>>(b, gam + l * HH, bet + l * HH,
                                              mean + l * HH, var + l * HH, 1);
    }

    // fused pooling + head
    k_pool_mlp<<<GG, 128>>>(l1w, l1b, l2w, l2b, out);
}

// round 12
// speedup vs baseline: 2.1897x; 1.0647x over previous
#include <cuda_runtime.h>
#include <cuda_bf16.h>

#define NN 50000
#define EE 600000
#define HH 128
#define GG 2048
#define FIN 11
#define LL 5
#define EPSV 1e-5f
#define SCAN_B 49   // ceil(NN/1024)

// ---------------- scratch (static device globals) ----------------
__device__ float        g_dinv[NN];
__device__ int          g_cnt[NN];
__device__ int          g_off[NN + 1];
__device__ int          g_cur[NN];
__device__ int2         g_csr[EE];            // {src, nrm-bits}
__device__ unsigned int g_hb[NN * (HH / 2)];  // h  bf16x2, [N][64]
__device__ unsigned int g_xb[NN * (HH / 2)];  // x  bf16x2, [N][64]
__device__ int          g_start[GG + 1];
__device__ int          g_part[64];

// ---------------- bf16 helpers ----------------
__device__ __forceinline__ unsigned packbf2(float a, float b) {
    unsigned r;
    asm("cvt.rn.bf16x2.f32 %0, %1, %2;" : "=r"(r) : "f"(b), "f"(a));
    return r;  // low half = a, high half = b
}
__device__ __forceinline__ void bfsplit2(float a, float b, unsigned& hi, unsigned& lo) {
    hi = packbf2(a, b);
    float ra = a - __uint_as_float(hi << 16);
    float rb = b - __uint_as_float(hi & 0xFFFF0000u);
    lo = packbf2(ra, rb);
}
__device__ __forceinline__ float bflo(unsigned w) { return __uint_as_float(w << 16); }
__device__ __forceinline__ float bfhi(unsigned w) { return __uint_as_float(w & 0xFFFF0000u); }

__device__ __forceinline__ void mma_bf16(float* d, const unsigned* a, const unsigned* b) {
    asm volatile(
        "mma.sync.aligned.m16n8k16.row.col.f32.bf16.bf16.f32 "
        "{%0,%1,%2,%3}, {%4,%5,%6,%7}, {%8,%9}, {%0,%1,%2,%3};"
        : "+f"(d[0]), "+f"(d[1]), "+f"(d[2]), "+f"(d[3])
        : "r"(a[0]), "r"(a[1]), "r"(a[2]), "r"(a[3]), "r"(b[0]), "r"(b[1]));
}

// ---------------- degree / CSR build ----------------
__global__ void k_zero_cnt() {
    int i = blockIdx.x * blockDim.x + threadIdx.x;
    if (i < NN) g_cnt[i] = 0;
}

__global__ void k_count(const int* __restrict__ ei) {
    int e = blockIdx.x * blockDim.x + threadIdx.x;
    if (e < EE) atomicAdd(&g_cnt[ei[EE + e]], 1);
}

// ---- coalesced 2-phase scan (phase 1 also computes dinv) ----
__global__ void k_scan1() {
    int t = threadIdx.x, b = blockIdx.x;
    int i = b * 1024 + t;
    int v = (i < NN) ? g_cnt[i] : 0;
    if (i < NN) g_dinv[i] = rsqrtf((float)v + 1.0f);   // +1 self-loop
    int lane = t & 31, wid = t >> 5;
    int x = v;
    #pragma unroll
    for (int d = 1; d < 32; d <<= 1) {
        int n = __shfl_up_sync(0xFFFFFFFF, x, d);
        if (lane >= d) x += n;
    }
    __shared__ int ws[32];
    if (lane == 31) ws[wid] = x;
    __syncthreads();
    if (wid == 0) {
        int w = ws[lane];
        #pragma unroll
        for (int d = 1; d < 32; d <<= 1) {
            int n = __shfl_up_sync(0xFFFFFFFF, w, d);
            if (lane >= d) w += n;
        }
        ws[lane] = w;
    }
    __syncthreads();
    int incl = x + (wid ? ws[wid - 1] : 0);
    if (i < NN) g_off[i] = incl - v;
    if (t == 1023) g_part[b] = incl;
}

// phase 2: each block redundantly prefixes the 49 partials, adds offsets,
// and builds per-graph boundaries (batch is sorted)
__global__ void k_scan3(const int* __restrict__ batch) {
    __shared__ int ps[SCAN_B];
    int t = threadIdx.x;
    if (t == 0) {
        int run = 0;
        #pragma unroll
        for (int j = 0; j < SCAN_B; j++) {
            int v = g_part[j];
            ps[j] = run;
            run += v;
        }
        if (blockIdx.x == 0) g_off[NN] = run;
    }
    __syncthreads();
    int i = blockIdx.x * blockDim.x + t;
    if (i >= NN) return;
    int o = g_off[i] + ps[i >> 10];
    g_off[i] = o;
    g_cur[i] = o;
    int b = batch[i];
    if (i == 0) {
        for (int g = 0; g <= b; g++) g_start[g] = 0;
    } else {
        int pb = batch[i - 1];
        for (int g = pb + 1; g <= b; g++) g_start[g] = i;
    }
    if (i == NN - 1) {
        for (int g = b + 1; g <= GG; g++) g_start[g] = NN;
    }
}

__global__ void k_fill(const int* __restrict__ ei) {
    int e = blockIdx.x * blockDim.x + threadIdx.x;
    if (e < EE) {
        int s = ei[e];
        int d = ei[EE + e];
        int p = atomicAdd(&g_cur[d], 1);
        g_csr[p] = make_int2(s, __float_as_int(g_dinv[s] * g_dinv[d]));
    }
}

// ---------------- GEMM: layer 0 (K = 11), writes g_hb ----------------
__global__ void k_gemm0(const float* __restrict__ X, const float* __restrict__ W0) {
    __shared__ float sW[FIN * HH];
    __shared__ float sx[16 * FIN];
    int t = threadIdx.x;
    int rowBase = blockIdx.x * 16;
    for (int idx = t; idx < FIN * HH; idx += 256) sW[idx] = W0[idx];
    if (t < 16 * FIN) {
        int r = rowBase + t / FIN;
        sx[t] = (r < NN) ? X[r * FIN + (t % FIN)] : 0.0f;
    }
    __syncthreads();
    int c = t & 127;
    int rh = t >> 7;
    float w[FIN];
    #pragma unroll
    for (int k = 0; k < FIN; k++) w[k] = sW[k * HH + c];
    #pragma unroll
    for (int i = 0; i < 8; i++) {
        int rloc = rh + 2 * i;
        int r = rowBase + rloc;
        if (r < NN) {
            float acc = 0.0f;
            #pragma unroll
            for (int k = 0; k < FIN; k++) acc += sx[rloc * FIN + k] * w[k];
            float other = __shfl_xor_sync(0xFFFFFFFF, acc, 1);
            if ((c & 1) == 0)
                g_hb[r * 64 + (c >> 1)] = packbf2(acc, other);
        }
    }
}

// ---------------- GEMM 128x128, 2-term bf16 (A from bf16 g_xb, B hi/lo split) ------
// g_xb @ W -> g_hb.  K chunked by 32 (16 bf16x2 words).
__global__ void __launch_bounds__(256) k_gemm_tc(const float* __restrict__ W) {
    __shared__ unsigned sA[128][20];                  // [row][k2] pitch 20
    __shared__ unsigned sBh[16][136], sBl[16][136];   // [k2][n]  pitch 136
    int t = threadIdx.x;
    int rowBase = blockIdx.x * 128;
    int lane = t & 31, w = t >> 5;
    int wm = w >> 1, wn = w & 1;
    int gq = lane >> 2, cq = lane & 3;

    float acc[2][8][4];
    #pragma unroll
    for (int mt = 0; mt < 2; mt++)
        #pragma unroll
        for (int nt = 0; nt < 8; nt++)
            #pragma unroll
            for (int k = 0; k < 4; k++) acc[mt][nt][k] = 0.0f;

    const float4* W4 = (const float4*)W;
    const uint4*  X4 = (const uint4*)g_xb;   // [N][16] uint4

    for (int kc = 0; kc < 4; kc++) {
        // A: 128 rows x 16 k2-words = 512 uint4; already bf16, direct copy
        #pragma unroll
        for (int i = 0; i < 2; i++) {
            int idx = t + 256 * i;             // 0..511
            int r = idx >> 2, c4 = idx & 3;
            int gr = rowBase + r;
            uint4 v = (gr < NN) ? X4[gr * 16 + kc * 4 + c4]
                                : make_uint4(0u, 0u, 0u, 0u);
            *(uint4*)&sA[r][c4 * 4] = v;
        }
        // B: 32 k x 128 n; hi/lo split, packed along k
        #pragma unroll
        for (int i = 0; i < 2; i++) {
            int idx = t + 256 * i;             // 0..511
            int k2 = idx >> 5, n4 = idx & 31;  // k2 0..15
            int kr0 = kc * 32 + k2 * 2;
            float4 v0 = W4[kr0 * 32 + n4];
            float4 v1 = W4[(kr0 + 1) * 32 + n4];
            unsigned h0, l0, h1, l1, h2, l2, h3, l3;
            bfsplit2(v0.x, v1.x, h0, l0);
            bfsplit2(v0.y, v1.y, h1, l1);
            bfsplit2(v0.z, v1.z, h2, l2);
            bfsplit2(v0.w, v1.w, h3, l3);
            int nb = n4 * 4;
            *(uint4*)&sBh[k2][nb] = make_uint4(h0, h1, h2, h3);
            *(uint4*)&sBl[k2][nb] = make_uint4(l0, l1, l2, l3);
        }
        __syncthreads();

        #pragma unroll
        for (int ks = 0; ks < 2; ks++) {
            int kb2 = ks * 8;
            unsigned bh[8][2], bl[8][2];
            #pragma unroll
            for (int nt = 0; nt < 8; nt++) {
                int n0 = wn * 64 + nt * 8 + gq;
                bh[nt][0] = sBh[kb2 + cq][n0];
                bh[nt][1] = sBh[kb2 + 4 + cq][n0];
                bl[nt][0] = sBl[kb2 + cq][n0];
                bl[nt][1] = sBl[kb2 + 4 + cq][n0];
            }
            unsigned ah[2][4];
            #pragma unroll
            for (int mt = 0; mt < 2; mt++) {
                int r0 = wm * 32 + mt * 16 + gq;
                ah[mt][0] = sA[r0][kb2 + cq];
                ah[mt][1] = sA[r0 + 8][kb2 + cq];
                ah[mt][2] = sA[r0][kb2 + 4 + cq];
                ah[mt][3] = sA[r0 + 8][kb2 + 4 + cq];
            }
            #pragma unroll
            for (int mt = 0; mt < 2; mt++)
                #pragma unroll
                for (int nt = 0; nt < 8; nt++) {
                    mma_bf16(acc[mt][nt], ah[mt], bh[nt]);
                    mma_bf16(acc[mt][nt], ah[mt], bl[nt]);
                }
        }
        __syncthreads();
    }

    // epilogue: write g_hb (bf16x2)
    #pragma unroll
    for (int mt = 0; mt < 2; mt++) {
        int r0 = rowBase + wm * 32 + mt * 16 + gq;
        #pragma unroll
        for (int nt = 0; nt < 8; nt++) {
            int col = wn * 64 + nt * 8 + cq * 2;
            if (r0 < NN)
                g_hb[r0 * 64 + (col >> 1)] = packbf2(acc[mt][nt][0], acc[mt][nt][1]);
            if (r0 + 8 < NN)
                g_hb[(r0 + 8) * 64 + (col >> 1)] = packbf2(acc[mt][nt][2], acc[mt][nt][3]);
        }
    }
}

// ---------------- aggregation: half-warp (16 lanes) per node, uint4 gathers ----------
__device__ __forceinline__ void bf8fma(float* acc, float w, uint4 p) {
    acc[0] += w * bflo(p.x);
    acc[1] += w * bfhi(p.x);
    acc[2] += w * bflo(p.y);
    acc[3] += w * bfhi(p.y);
    acc[4] += w * bflo(p.z);
    acc[5] += w * bfhi(p.z);
    acc[6] += w * bflo(p.w);
    acc[7] += w * bfhi(p.w);
}

__global__ void k_agg(const float* __restrict__ bvec,
                      const float* __restrict__ gamma, const float* __restrict__ beta,
                      const float* __restrict__ mean,  const float* __restrict__ var,
                      int residual) {
    int idx = blockIdx.x * blockDim.x + threadIdx.x;
    int node = idx >> 4;
    if (node >= NN) return;
    int l16 = threadIdx.x & 15;
    const uint4* hb4 = (const uint4*)g_hb;   // [N][16] uint4
    uint4* xb4 = (uint4*)g_xb;

    float di = g_dinv[node];
    float self = di * di;
    float acc[8] = {0, 0, 0, 0, 0, 0, 0, 0};
    bf8fma(acc, self, hb4[node * 16 + l16]);

    int s0 = g_off[node], s1 = g_off[node + 1];
    int e = s0;
    for (; e + 2 <= s1; e += 2) {
        int2 sa = g_csr[e];
        int2 sb = g_csr[e + 1];
        uint4 pa = hb4[sa.x * 16 + l16];
        uint4 pb = hb4[sb.x * 16 + l16];
        bf8fma(acc, __int_as_float(sa.y), pa);
        bf8fma(acc, __int_as_float(sb.y), pb);
    }
    if (e < s1) {
        int2 se = g_csr[e];
        bf8fma(acc, __int_as_float(se.y), hb4[se.x * 16 + l16]);
    }

    int c0 = 8 * l16;
    float4 bv0 = *(const float4*)&bvec[c0],  bv1 = *(const float4*)&bvec[c0 + 4];
    float4 gm0 = *(const float4*)&gamma[c0], gm1 = *(const float4*)&gamma[c0 + 4];
    float4 bt0 = *(const float4*)&beta[c0],  bt1 = *(const float4*)&beta[c0 + 4];
    float4 mn0 = *(const float4*)&mean[c0],  mn1 = *(const float4*)&mean[c0 + 4];
    float4 vr0 = *(const float4*)&var[c0],   vr1 = *(const float4*)&var[c0 + 4];

    float b8[8]  = {bv0.x, bv0.y, bv0.z, bv0.w, bv1.x, bv1.y, bv1.z, bv1.w};
    float g8[8]  = {gm0.x, gm0.y, gm0.z, gm0.w, gm1.x, gm1.y, gm1.z, gm1.w};
    float t8[8]  = {bt0.x, bt0.y, bt0.z, bt0.w, bt1.x, bt1.y, bt1.z, bt1.w};
    float m8[8]  = {mn0.x, mn0.y, mn0.z, mn0.w, mn1.x, mn1.y, mn1.z, mn1.w};
    float v8[8]  = {vr0.x, vr0.y, vr0.z, vr0.w, vr1.x, vr1.y, vr1.z, vr1.w};

    float r8[8];
    #pragma unroll
    for (int j = 0; j < 8; j++) {
        float sc = g8[j] * rsqrtf(v8[j] + EPSV);
        r8[j] = fmaxf((acc[j] + b8[j] - m8[j]) * sc + t8[j], 0.0f);
    }

    if (residual) {
        uint4 xp = xb4[node * 16 + l16];
        r8[0] += bflo(xp.x); r8[1] += bfhi(xp.x);
        r8[2] += bflo(xp.y); r8[3] += bfhi(xp.y);
        r8[4] += bflo(xp.z); r8[5] += bfhi(xp.z);
        r8[6] += bflo(xp.w); r8[7] += bfhi(xp.w);
    }
    uint4 outw;
    outw.x = packbf2(r8[0], r8[1]);
    outw.y = packbf2(r8[2], r8[3]);
    outw.z = packbf2(r8[4], r8[5]);
    outw.w = packbf2(r8[6], r8[7]);
    xb4[node * 16 + l16] = outw;
}

// ---------------- fused pooling + MLP head (block per graph) ----------------
__global__ void k_pool_mlp(const float* __restrict__ l1w, const float* __restrict__ l1b,
                           const float* __restrict__ l2w, const float* __restrict__ l2b,
                           float* __restrict__ out) {
    int g = blockIdx.x;
    int t = threadIdx.x;  // 128
    __shared__ float sp[HH];
    __shared__ float red[64];

    int s = g_start[g], e = g_start[g + 1];
    int wi = t >> 1, hi = t & 1;
    float sum = 0.0f;
    for (int r = s; r < e; r++) {
        unsigned w = g_xb[r * 64 + wi];
        sum += hi ? bfhi(w) : bflo(w);
    }
    float inv = 1.0f / fmaxf((float)(e - s), 1.0f);
    sp[t] = sum * inv;
    __syncthreads();

    if (t < 64) {
        float acc = l1b[t];
        #pragma unroll 8
        for (int k = 0; k < HH; k++) acc += sp[k] * l1w[k * 64 + t];
        float h1 = fmaxf(acc, 0.0f);
        red[t] = h1 * l2w[t];
    }
    __syncthreads();
    if (t < 32) {
        float v = red[t] + red[t + 32];
        #pragma unroll
        for (int d = 16; d > 0; d >>= 1) v += __shfl_down_sync(0xFFFFFFFF, v, d);
        if (t == 0) out[g] = v + l2b[0];
    }
}

// ---------------- launch ----------------
extern "C" void kernel_launch(void* const* d_in, const int* in_sizes, int n_in,
                              void* d_out, int out_size) {
    const float* x     = (const float*)d_in[0];
    const int*   ei    = (const int*)d_in[1];
    const int*   batch = (const int*)d_in[2];
    const float* W0    = (const float*)d_in[3];
    const float* b0    = (const float*)d_in[4];
    const float* Ws    = (const float*)d_in[5];
    const float* bs    = (const float*)d_in[6];
    const float* gam   = (const float*)d_in[7];
    const float* bet   = (const float*)d_in[8];
    const float* mean  = (const float*)d_in[9];
    const float* var   = (const float*)d_in[10];
    const float* l1w   = (const float*)d_in[11];
    const float* l1b   = (const float*)d_in[12];
    const float* l2w   = (const float*)d_in[13];
    const float* l2b   = (const float*)d_in[14];
    float* out = (float*)d_out;

    // graph prep
    k_zero_cnt<<<(NN + 255) / 256, 256>>>();
    k_count<<<(EE + 255) / 256, 256>>>(ei);
    k_scan1<<<SCAN_B, 1024>>>();
    k_scan3<<<(NN + 255) / 256, 256>>>(batch);
    k_fill<<<(EE + 255) / 256, 256>>>(ei);

    // layer 0
    k_gemm0<<<(NN + 15) / 16, 256>>>(x, W0);
    k_agg<<<(NN * 16 + 255) / 256, 256>>>(b0, gam, bet, mean, var, 0);

    // layers 1..4 (bf16 2-term tensor-core GEMM)
    for (int l = 1; l < LL; l++) {
        const float* W = Ws + (l - 1) * HH * HH;
        const float* b = bs + (l - 1) * HH;
        k_gemm_tc<<<(NN + 127) / 128, 256>>>(W);
        k_agg<<<(NN * 16 + 255) / 256, 256>>>(b, gam + l * HH, bet + l * HH,
                                              mean + l * HH, var + l * HH, 1);
    }

    // fused pooling + head
    k_pool_mlp<<<GG, 128>>>(l1w, l1b, l2w, l2b, out);
}